// round 3
// baseline (speedup 1.0000x reference)
#include <cuda_runtime.h>
#include <cuda_bf16.h>
#include <cstdint>

// Problem constants
#define C_IN   128
#define OC     768            // 256 q + 256 k + 256 v stacked
#define NP     36864          // 192*192 pixels
#define HH     192
#define WW     192
#define NHEAD  8

// Scratch: q rows [0,256), k rows [256,512), v rows [512,768), each [ch][pixel]
__device__ float g_qkv[(size_t)OC * NP];
__device__ float g_t[(size_t)NHEAD * NP];

__device__ __constant__ int c_dh[9] = {-1,-1,-1, 0,0,0, 1,1,1};
__device__ __constant__ int c_dw[9] = {-1, 0, 1,-1,0,1,-1,0,1};

// ---------------------------------------------------------------------------
// Kernel 1: fused QKV projection GEMM.  out[o][p] = sum_c W[o][c] * x[c][p]
// Tile 128(out-ch) x 128(pixels), K=128 in 4 chunks of 32. 256 threads,
// each computes an 8x8 micro-tile.
// ---------------------------------------------------------------------------
__global__ __launch_bounds__(256) void gemm_qkv(
    const float* __restrict__ x,
    const float* __restrict__ wq,
    const float* __restrict__ wk,
    const float* __restrict__ wv)
{
    __shared__ float Wt[32][132];   // [k][r] transposed weight chunk (+4 pad)
    __shared__ float Xs[32][128];   // [k][p]

    const int bp  = blockIdx.x;     // pixel tile  (288)
    const int bo  = blockIdx.y;     // out-ch tile (6)
    const int tid = threadIdx.x;
    const int tx  = tid & 15;       // pixel dir
    const int ty  = tid >> 4;       // out-ch dir

    float acc[8][8];
#pragma unroll
    for (int i = 0; i < 8; i++)
#pragma unroll
        for (int j = 0; j < 8; j++) acc[i][j] = 0.f;

    for (int kc = 0; kc < 4; kc++) {
        // ---- load W chunk: rows bo*128..+128, cols kc*32..+32, transposed ----
#pragma unroll
        for (int l = 0; l < 4; l++) {
            int i  = tid + l * 256;          // 0..1023 float4 slots
            int r  = i >> 3;                 // 0..127 local out-ch
            int c4 = i & 7;                  // 0..7  float4 within 32 cols
            int rg = bo * 128 + r;
            const float* wsrc = (rg < 256) ? (wq + (size_t)rg * 128)
                              : (rg < 512) ? (wk + (size_t)(rg - 256) * 128)
                                           : (wv + (size_t)(rg - 512) * 128);
            float4 v = *(const float4*)(wsrc + kc * 32 + c4 * 4);
            Wt[c4 * 4 + 0][r] = v.x;
            Wt[c4 * 4 + 1][r] = v.y;
            Wt[c4 * 4 + 2][r] = v.z;
            Wt[c4 * 4 + 3][r] = v.w;
        }
        // ---- load X chunk: Xs[k][p] = x[(kc*32+k)*NP + bp*128 + p] ----
#pragma unroll
        for (int l = 0; l < 4; l++) {
            int i  = tid + l * 256;          // 0..1023 float4 slots
            int k  = i >> 5;                 // 0..31
            int p4 = i & 31;                 // 0..31
            *(float4*)&Xs[k][p4 * 4] =
                *(const float4*)(x + (size_t)(kc * 32 + k) * NP + bp * 128 + p4 * 4);
        }
        __syncthreads();

#pragma unroll 8
        for (int k = 0; k < 32; k++) {
            float a[8], b[8];
            *(float4*)&a[0] = *(float4*)&Wt[k][ty * 8];
            *(float4*)&a[4] = *(float4*)&Wt[k][ty * 8 + 4];
            *(float4*)&b[0] = *(float4*)&Xs[k][tx * 8];
            *(float4*)&b[4] = *(float4*)&Xs[k][tx * 8 + 4];
#pragma unroll
            for (int i = 0; i < 8; i++)
#pragma unroll
                for (int j = 0; j < 8; j++)
                    acc[i][j] += a[i] * b[j];
        }
        __syncthreads();
    }

    // ---- store ----
#pragma unroll
    for (int i = 0; i < 8; i++) {
        int rg = bo * 128 + ty * 8 + i;
        float* dst = g_qkv + (size_t)rg * NP + bp * 128 + tx * 8;
        *(float4*)(dst)     = make_float4(acc[i][0], acc[i][1], acc[i][2], acc[i][3]);
        *(float4*)(dst + 4) = make_float4(acc[i][4], acc[i][5], acc[i][6], acc[i][7]);
    }
}

// ---------------------------------------------------------------------------
// Kernel 2: per-pixel per-head q.k score:  t[head][p] = (sum_d q*k) / 16
// ---------------------------------------------------------------------------
__global__ __launch_bounds__(256) void qk_dot()
{
    const int p    = blockIdx.x * 256 + threadIdx.x;   // grid.x = 144 -> p < 36864
    const int head = blockIdx.y;
    const float* q = g_qkv + (size_t)(head * 32) * NP + p;
    const float* k = g_qkv + (size_t)(256 + head * 32) * NP + p;
    float s = 0.f;
#pragma unroll
    for (int d = 0; d < 32; d++)
        s += q[(size_t)d * NP] * k[(size_t)d * NP];
    g_t[(size_t)head * NP + p] = s * 0.0625f;   // / TEMPER (=16)
}

// ---------------------------------------------------------------------------
// Kernel 3: 3x3 regional softmax + weighted V sum.
// Block = (one image row h) x (head-group of 2 heads = 64 channels).
// Phase 1: softmax weights for 2 heads x 192 pixels into smem.
// Phase 2: 64 channels x 192 pixels outputs.
// NOTE: out-of-bounds slots contribute score 0 (exp(0-m)) to the softmax
// (zero padding makes qk = 0, not -inf), and OOB v contributes 0.
// ---------------------------------------------------------------------------
__global__ __launch_bounds__(256) void attn(float* __restrict__ out)
{
    __shared__ float w9s[9][2][192];   // [slot][head_local][w]

    const int h   = blockIdx.x;        // 0..191
    const int bg  = blockIdx.y;        // 0..3 head group
    const int tid = threadIdx.x;

    // ---- phase 1: softmax weights ----
    for (int i = tid; i < 2 * 192; i += 256) {
        int hl   = i / 192;
        int w    = i - hl * 192;
        int head = bg * 2 + hl;
        float sc[9];
#pragma unroll
        for (int s = 0; s < 9; s++) {
            int hh = h + c_dh[s];
            int ww = w + c_dw[s];
            float v = 0.f;
            if ((unsigned)hh < 192u && (unsigned)ww < 192u)
                v = g_t[(size_t)head * NP + hh * WW + ww];
            sc[s] = v;
        }
        float m = sc[0];
#pragma unroll
        for (int s = 1; s < 9; s++) m = fmaxf(m, sc[s]);
        float sum = 0.f;
#pragma unroll
        for (int s = 0; s < 9; s++) { float e = __expf(sc[s] - m); sc[s] = e; sum += e; }
        float inv = 1.0f / sum;
#pragma unroll
        for (int s = 0; s < 9; s++) w9s[s][hl][w] = sc[s] * inv;
    }
    __syncthreads();

    // ---- phase 2: weighted V gather ----
    for (int i = tid; i < 64 * 192; i += 256) {
        int cl = i / 192;
        int w  = i - cl * 192;
        int ch = bg * 64 + cl;
        int hl = cl >> 5;
        float acc = 0.f;
#pragma unroll
        for (int s = 0; s < 9; s++) {
            int hh = h + c_dh[s];
            int ww = w + c_dw[s];
            float vv = 0.f;
            if ((unsigned)hh < 192u && (unsigned)ww < 192u)
                vv = g_qkv[(size_t)(512 + ch) * NP + hh * WW + ww];
            acc += w9s[s][hl][w] * vv;
        }
        out[(size_t)ch * NP + h * WW + w] = acc;
    }
}

// ---------------------------------------------------------------------------
extern "C" void kernel_launch(void* const* d_in, const int* in_sizes, int n_in,
                              void* d_out, int out_size)
{
    const float* x  = (const float*)d_in[0];
    const float* wq = (const float*)d_in[1];
    const float* wk = (const float*)d_in[2];
    const float* wv = (const float*)d_in[3];
    float* out = (float*)d_out;

    dim3 g1(NP / 128, OC / 128);     // (288, 6)
    gemm_qkv<<<g1, 256>>>(x, wq, wk, wv);

    dim3 g2(NP / 256, NHEAD);        // (144, 8)
    qk_dot<<<g2, 256>>>();

    dim3 g3(HH, 4);                  // (192, 4)
    attn<<<g3, 256>>>(out);
}

// round 4
// speedup vs baseline: 1.5495x; 1.5495x over previous
#include <cuda_runtime.h>
#include <cuda_bf16.h>
#include <cstdint>

// Problem constants
#define C_IN   128
#define OC     768            // 256 q + 256 k + 256 v stacked
#define NP     36864          // 192*192 pixels
#define HH     192
#define WW     192
#define NHEAD  8

// Scratch: q rows [0,256), k rows [256,512), v rows [512,768), each [ch][pixel]
__device__ float g_qkv[(size_t)OC * NP];
__device__ float g_t[(size_t)NHEAD * NP];

__device__ __constant__ int c_dh[9] = {-1,-1,-1, 0,0,0, 1,1,1};
__device__ __constant__ int c_dw[9] = {-1, 0, 1,-1,0,1,-1,0,1};

// ---------------------------------------------------------------------------
// bf16 hi/lo split helper: f ~= hi + lo with |err| ~ 2^-18 |f|
// ---------------------------------------------------------------------------
__device__ __forceinline__ void bf16_split(float f, unsigned short& h, unsigned short& l)
{
    __nv_bfloat16 hb = __float2bfloat16(f);
    float r = f - __bfloat162float(hb);
    __nv_bfloat16 lb = __float2bfloat16(r);
    h = __bfloat16_as_ushort(hb);
    l = __bfloat16_as_ushort(lb);
}

__device__ __forceinline__ void mma16816(float c[4],
                                         uint32_t a0, uint32_t a1, uint32_t a2, uint32_t a3,
                                         uint32_t b0, uint32_t b1)
{
    asm volatile(
        "mma.sync.aligned.m16n8k16.row.col.f32.bf16.bf16.f32 "
        "{%0,%1,%2,%3}, {%4,%5,%6,%7}, {%8,%9}, {%0,%1,%2,%3};\n"
        : "+f"(c[0]), "+f"(c[1]), "+f"(c[2]), "+f"(c[3])
        : "r"(a0), "r"(a1), "r"(a2), "r"(a3), "r"(b0), "r"(b1));
}

// ---------------------------------------------------------------------------
// Kernel 1: fused QKV projection GEMM via tensor cores (bf16 split, 3 terms).
//   out[o][p] = sum_c W[o][c] * x[c][p]
// CTA tile 128(o) x 128(p), K=128 in 4 chunks of 32. 256 threads = 8 warps,
// warps arranged 2(m) x 4(n), warp tile 64 x 32 -> 4x4 m16n8k16 subtiles.
// A (=W) smem: [128 rows][32 k]. bf16, row stride 80 B (8-el pad, 16B aligned).
// B (=X) smem: [128 p][32 k] bf16 (k-contiguous per pixel), row stride 68 B.
// ---------------------------------------------------------------------------
#define ROWA 80
#define ROWB 68

__global__ __launch_bounds__(256) void gemm_qkv(
    const float* __restrict__ x,
    const float* __restrict__ wq,
    const float* __restrict__ wk,
    const float* __restrict__ wv)
{
    __shared__ __align__(16) unsigned char sAhi[128 * ROWA];
    __shared__ __align__(16) unsigned char sAlo[128 * ROWA];
    __shared__ __align__(16) unsigned char sBhi[128 * ROWB];
    __shared__ __align__(16) unsigned char sBlo[128 * ROWB];

    const int bp   = blockIdx.x;     // pixel tile  (288)
    const int bo   = blockIdx.y;     // out-ch tile (6)
    const int tid  = threadIdx.x;
    const int wid  = tid >> 5;
    const int lane = tid & 31;
    const int g    = lane >> 2;      // 0..7
    const int q    = lane & 3;       // 0..3
    const int warp_m = wid >> 2;     // 0..1
    const int warp_n = wid & 3;      // 0..3

    // A-loader role: o = tid>>1 (0..127), kh = tid&1 (k half of 16)
    const int alo_o  = tid >> 1;
    const int alo_kh = tid & 1;
    const int rg = bo * 128 + alo_o;                 // global out-channel
    const float* wsrc = (rg < 256) ? (wq + (size_t)rg * 128)
                      : (rg < 512) ? (wk + (size_t)(rg - 256) * 128)
                                   : (wv + (size_t)(rg - 512) * 128);

    // B-loader role: p = tid&127, kh = tid>>7
    const int blo_p  = tid & 127;
    const int blo_kh = tid >> 7;

    float acc[4][4][4];
#pragma unroll
    for (int i = 0; i < 4; i++)
#pragma unroll
        for (int j = 0; j < 4; j++)
#pragma unroll
            for (int r = 0; r < 4; r++) acc[i][j][r] = 0.f;

    for (int kc = 0; kc < 4; kc++) {
        const int c0 = kc * 32;

        // ---- load + split A chunk: W rows [bo*128,+128), k [c0,+32) ----
        {
            const float* wrow = wsrc + c0 + alo_kh * 16;
            float v[16];
#pragma unroll
            for (int i = 0; i < 4; i++) {
                float4 f4 = ((const float4*)wrow)[i];
                v[4*i+0] = f4.x; v[4*i+1] = f4.y; v[4*i+2] = f4.z; v[4*i+3] = f4.w;
            }
            uint32_t hw[8], lw[8];
#pragma unroll
            for (int i = 0; i < 8; i++) {
                unsigned short h0, l0, h1, l1;
                bf16_split(v[2*i],   h0, l0);
                bf16_split(v[2*i+1], h1, l1);
                hw[i] = (uint32_t)h0 | ((uint32_t)h1 << 16);
                lw[i] = (uint32_t)l0 | ((uint32_t)l1 << 16);
            }
            uint32_t off = alo_o * ROWA + alo_kh * 32;
            *(uint4*)(sAhi + off)      = make_uint4(hw[0], hw[1], hw[2], hw[3]);
            *(uint4*)(sAhi + off + 16) = make_uint4(hw[4], hw[5], hw[6], hw[7]);
            *(uint4*)(sAlo + off)      = make_uint4(lw[0], lw[1], lw[2], lw[3]);
            *(uint4*)(sAlo + off + 16) = make_uint4(lw[4], lw[5], lw[6], lw[7]);
        }

        // ---- load + split B chunk: x rows [c0,+32) (k), cols [bp*128,+128) ----
        {
            const float* xcol = x + (size_t)(c0 + blo_kh * 16) * NP + bp * 128 + blo_p;
            float v[16];
#pragma unroll
            for (int k = 0; k < 16; k++) v[k] = xcol[(size_t)k * NP];
            uint32_t base = blo_p * ROWB + blo_kh * 32;
#pragma unroll
            for (int k = 0; k < 16; k++) {
                unsigned short h, l;
                bf16_split(v[k], h, l);
                *(unsigned short*)(sBhi + base + 2*k) = h;
                *(unsigned short*)(sBlo + base + 2*k) = l;
            }
        }
        __syncthreads();

        // ---- 2 k-steps of 16 within the chunk ----
#pragma unroll
        for (int ks = 0; ks < 2; ks++) {
            const int klb = ks * 32;     // byte offset of k-step within row

            uint32_t ahi[4][4], alo_[4][4];
#pragma unroll
            for (int i = 0; i < 4; i++) {
                uint32_t r0 = (warp_m * 64 + i * 16 + g) * ROWA + klb + 4 * q;
                uint32_t r1 = r0 + 8 * ROWA;
                ahi[i][0] = *(const uint32_t*)(sAhi + r0);
                ahi[i][1] = *(const uint32_t*)(sAhi + r1);
                ahi[i][2] = *(const uint32_t*)(sAhi + r0 + 16);
                ahi[i][3] = *(const uint32_t*)(sAhi + r1 + 16);
                alo_[i][0] = *(const uint32_t*)(sAlo + r0);
                alo_[i][1] = *(const uint32_t*)(sAlo + r1);
                alo_[i][2] = *(const uint32_t*)(sAlo + r0 + 16);
                alo_[i][3] = *(const uint32_t*)(sAlo + r1 + 16);
            }
#pragma unroll
            for (int j = 0; j < 4; j++) {
                uint32_t cb = (warp_n * 32 + j * 8 + g) * ROWB + klb + 4 * q;
                uint32_t bh0 = *(const uint32_t*)(sBhi + cb);
                uint32_t bh1 = *(const uint32_t*)(sBhi + cb + 16);
                uint32_t bl0 = *(const uint32_t*)(sBlo + cb);
                uint32_t bl1 = *(const uint32_t*)(sBlo + cb + 16);
#pragma unroll
                for (int i = 0; i < 4; i++) {
                    mma16816(acc[i][j], ahi[i][0], ahi[i][1], ahi[i][2], ahi[i][3], bh0, bh1);
                    mma16816(acc[i][j], ahi[i][0], ahi[i][1], ahi[i][2], ahi[i][3], bl0, bl1);
                    mma16816(acc[i][j], alo_[i][0], alo_[i][1], alo_[i][2], alo_[i][3], bh0, bh1);
                }
            }
        }
        __syncthreads();
    }

    // ---- epilogue: D element (row g/g+8, col 2q/2q+1) per subtile ----
#pragma unroll
    for (int i = 0; i < 4; i++) {
        int o = bo * 128 + warp_m * 64 + i * 16 + g;
#pragma unroll
        for (int j = 0; j < 4; j++) {
            int p = bp * 128 + warp_n * 32 + j * 8 + 2 * q;
            *(float2*)(g_qkv + (size_t)o * NP + p)       = make_float2(acc[i][j][0], acc[i][j][1]);
            *(float2*)(g_qkv + (size_t)(o + 8) * NP + p) = make_float2(acc[i][j][2], acc[i][j][3]);
        }
    }
}

// ---------------------------------------------------------------------------
// Kernel 2: per-pixel per-head q.k score:  t[head][p] = (sum_d q*k) / 16
// ---------------------------------------------------------------------------
__global__ __launch_bounds__(256) void qk_dot()
{
    const int p    = blockIdx.x * 256 + threadIdx.x;   // grid.x = 144 -> p < 36864
    const int head = blockIdx.y;
    const float* qp = g_qkv + (size_t)(head * 32) * NP + p;
    const float* kp = g_qkv + (size_t)(256 + head * 32) * NP + p;
    float s = 0.f;
#pragma unroll
    for (int d = 0; d < 32; d++)
        s += qp[(size_t)d * NP] * kp[(size_t)d * NP];
    g_t[(size_t)head * NP + p] = s * 0.0625f;   // / TEMPER (=16)
}

// ---------------------------------------------------------------------------
// Kernel 3: 3x3 regional softmax + weighted V sum.
// OOB slots contribute score 0 (exp(0-m)) to the softmax (zero padding makes
// qk = 0, not -inf); OOB v contributes 0.
// ---------------------------------------------------------------------------
__global__ __launch_bounds__(256) void attn(float* __restrict__ out)
{
    __shared__ float w9s[9][2][192];   // [slot][head_local][w]

    const int h   = blockIdx.x;        // 0..191
    const int bg  = blockIdx.y;        // 0..3 head group
    const int tid = threadIdx.x;

    // ---- phase 1: softmax weights ----
    for (int i = tid; i < 2 * 192; i += 256) {
        int hl   = i / 192;
        int w    = i - hl * 192;
        int head = bg * 2 + hl;
        float sc[9];
#pragma unroll
        for (int s = 0; s < 9; s++) {
            int hh = h + c_dh[s];
            int ww = w + c_dw[s];
            float v = 0.f;
            if ((unsigned)hh < 192u && (unsigned)ww < 192u)
                v = g_t[(size_t)head * NP + hh * WW + ww];
            sc[s] = v;
        }
        float m = sc[0];
#pragma unroll
        for (int s = 1; s < 9; s++) m = fmaxf(m, sc[s]);
        float sum = 0.f;
#pragma unroll
        for (int s = 0; s < 9; s++) { float e = __expf(sc[s] - m); sc[s] = e; sum += e; }
        float inv = 1.0f / sum;
#pragma unroll
        for (int s = 0; s < 9; s++) w9s[s][hl][w] = sc[s] * inv;
    }
    __syncthreads();

    // ---- phase 2: weighted V gather ----
    for (int i = tid; i < 64 * 192; i += 256) {
        int cl = i / 192;
        int w  = i - cl * 192;
        int ch = bg * 64 + cl;
        int hl = cl >> 5;
        float accv = 0.f;
#pragma unroll
        for (int s = 0; s < 9; s++) {
            int hh = h + c_dh[s];
            int ww = w + c_dw[s];
            float vv = 0.f;
            if ((unsigned)hh < 192u && (unsigned)ww < 192u)
                vv = g_qkv[(size_t)(512 + ch) * NP + hh * WW + ww];
            accv += w9s[s][hl][w] * vv;
        }
        out[(size_t)ch * NP + h * WW + w] = accv;
    }
}

// ---------------------------------------------------------------------------
extern "C" void kernel_launch(void* const* d_in, const int* in_sizes, int n_in,
                              void* d_out, int out_size)
{
    const float* x  = (const float*)d_in[0];
    const float* wq = (const float*)d_in[1];
    const float* wk = (const float*)d_in[2];
    const float* wv = (const float*)d_in[3];
    float* out = (float*)d_out;

    dim3 g1(NP / 128, OC / 128);     // (288, 6)
    gemm_qkv<<<g1, 256>>>(x, wq, wk, wv);

    dim3 g2(NP / 256, NHEAD);        // (144, 8)
    qk_dot<<<g2, 256>>>();

    dim3 g3(HH, 4);                  // (192, 4)
    attn<<<g3, 256>>>(out);
}

// round 5
// speedup vs baseline: 2.0627x; 1.3311x over previous
#include <cuda_runtime.h>
#include <cuda_bf16.h>
#include <cstdint>

// Problem constants
#define C_IN   128
#define OC     768            // 256 q + 256 k + 256 v stacked
#define NP     36864          // 192*192 pixels
#define HH     192
#define WW     192
#define NHEAD  8

// Scratch: q rows [0,256), k rows [256,512), v rows [512,768), each [ch][pixel]
__device__ float g_qkv[(size_t)OC * NP];
__device__ float g_t[(size_t)NHEAD * NP];

// ---------------------------------------------------------------------------
// bf16 hi/lo split helper: f ~= hi + lo with |err| ~ 2^-18 |f|
// ---------------------------------------------------------------------------
__device__ __forceinline__ void bf16_split(float f, unsigned short& h, unsigned short& l)
{
    __nv_bfloat16 hb = __float2bfloat16(f);
    float r = f - __bfloat162float(hb);
    __nv_bfloat16 lb = __float2bfloat16(r);
    h = __bfloat16_as_ushort(hb);
    l = __bfloat16_as_ushort(lb);
}

__device__ __forceinline__ void mma16816(float c[4],
                                         uint32_t a0, uint32_t a1, uint32_t a2, uint32_t a3,
                                         uint32_t b0, uint32_t b1)
{
    asm volatile(
        "mma.sync.aligned.m16n8k16.row.col.f32.bf16.bf16.f32 "
        "{%0,%1,%2,%3}, {%4,%5,%6,%7}, {%8,%9}, {%0,%1,%2,%3};\n"
        : "+f"(c[0]), "+f"(c[1]), "+f"(c[2]), "+f"(c[3])
        : "r"(a0), "r"(a1), "r"(a2), "r"(a3), "r"(b0), "r"(b1));
}

__device__ __forceinline__ void ldsm_x4(uint32_t& r0, uint32_t& r1, uint32_t& r2, uint32_t& r3,
                                        uint32_t saddr)
{
    asm volatile("ldmatrix.sync.aligned.m8n8.x4.shared.b16 {%0,%1,%2,%3}, [%4];"
                 : "=r"(r0), "=r"(r1), "=r"(r2), "=r"(r3) : "r"(saddr));
}

__device__ __forceinline__ void ldsm_x2(uint32_t& r0, uint32_t& r1, uint32_t saddr)
{
    asm volatile("ldmatrix.sync.aligned.m8n8.x2.shared.b16 {%0,%1}, [%2];"
                 : "=r"(r0), "=r"(r1) : "r"(saddr));
}

// ---------------------------------------------------------------------------
// Kernel 1: fused QKV projection GEMM via tensor cores (bf16 split, 3 terms).
//   out[o][p] = sum_c W[o][c] * x[c][p]
// CTA tile 128(o) x 128(p), K=128 in 4 chunks of 32. 256 threads = 8 warps,
// warps 2(m) x 4(n), warp tile 64 x 32 -> 4x4 m16n8k16 subtiles.
// All smem rows stride 80 B (32 B data + pad): 16B-aligned rows, and the 8
// ldmatrix row addresses at stride 5x16B mod 8 banks are conflict-free.
// ---------------------------------------------------------------------------
#define ROWA 80
#define ROWB 80

__global__ __launch_bounds__(256) void gemm_qkv(
    const float* __restrict__ x,
    const float* __restrict__ wq,
    const float* __restrict__ wk,
    const float* __restrict__ wv)
{
    __shared__ __align__(16) unsigned char sAhi[128 * ROWA];
    __shared__ __align__(16) unsigned char sAlo[128 * ROWA];
    __shared__ __align__(16) unsigned char sBhi[128 * ROWB];
    __shared__ __align__(16) unsigned char sBlo[128 * ROWB];

    const int bp   = blockIdx.x;     // pixel tile  (288)
    const int bo   = blockIdx.y;     // out-ch tile (6)
    const int tid  = threadIdx.x;
    const int wid  = tid >> 5;
    const int lane = tid & 31;
    const int warp_m = wid >> 2;     // 0..1
    const int warp_n = wid & 3;      // 0..3

    // A-loader role: o = tid>>1 (0..127), kh = tid&1 (k half of 16)
    const int alo_o  = tid >> 1;
    const int alo_kh = tid & 1;
    const int rg = bo * 128 + alo_o;                 // global out-channel
    const float* wsrc = (rg < 256) ? (wq + (size_t)rg * 128)
                      : (rg < 512) ? (wk + (size_t)(rg - 256) * 128)
                                   : (wv + (size_t)(rg - 512) * 128);

    // B-loader role: p = tid&127, kh = tid>>7
    const int blo_p  = tid & 127;
    const int blo_kh = tid >> 7;

    // ldmatrix lane -> address roles
    const int a_mat  = lane >> 3;                    // 0..3
    const int a_rowl = ((a_mat & 1) << 3) + (lane & 7);
    const int a_seg  = a_mat >> 1;
    const uint32_t sAhi_b = (uint32_t)__cvta_generic_to_shared(sAhi);
    const uint32_t sAlo_b = (uint32_t)__cvta_generic_to_shared(sAlo);
    const uint32_t sBhi_b = (uint32_t)__cvta_generic_to_shared(sBhi);
    const uint32_t sBlo_b = (uint32_t)__cvta_generic_to_shared(sBlo);
    const uint32_t aBaseOff = (uint32_t)(warp_m * 64 + a_rowl) * ROWA + a_seg * 16;
    const int b_rowl = lane & 7;
    const int b_seg  = (lane >> 3) & 1;
    const uint32_t bBaseOff = (uint32_t)(warp_n * 32 + b_rowl) * ROWB + b_seg * 16;

    float acc[4][4][4];
#pragma unroll
    for (int i = 0; i < 4; i++)
#pragma unroll
        for (int j = 0; j < 4; j++)
#pragma unroll
            for (int r = 0; r < 4; r++) acc[i][j][r] = 0.f;

    for (int kc = 0; kc < 4; kc++) {
        const int c0 = kc * 32;

        // ---- load + split A chunk: W rows [bo*128,+128), k [c0,+32) ----
        {
            const float* wrow = wsrc + c0 + alo_kh * 16;
            float v[16];
#pragma unroll
            for (int i = 0; i < 4; i++) {
                float4 f4 = ((const float4*)wrow)[i];
                v[4*i+0] = f4.x; v[4*i+1] = f4.y; v[4*i+2] = f4.z; v[4*i+3] = f4.w;
            }
            uint32_t hw[8], lw[8];
#pragma unroll
            for (int i = 0; i < 8; i++) {
                unsigned short h0, l0, h1, l1;
                bf16_split(v[2*i],   h0, l0);
                bf16_split(v[2*i+1], h1, l1);
                hw[i] = (uint32_t)h0 | ((uint32_t)h1 << 16);
                lw[i] = (uint32_t)l0 | ((uint32_t)l1 << 16);
            }
            uint32_t off = alo_o * ROWA + alo_kh * 32;
            *(uint4*)(sAhi + off)      = make_uint4(hw[0], hw[1], hw[2], hw[3]);
            *(uint4*)(sAhi + off + 16) = make_uint4(hw[4], hw[5], hw[6], hw[7]);
            *(uint4*)(sAlo + off)      = make_uint4(lw[0], lw[1], lw[2], lw[3]);
            *(uint4*)(sAlo + off + 16) = make_uint4(lw[4], lw[5], lw[6], lw[7]);
        }

        // ---- load + split B chunk: x rows [c0,+32) (k), cols [bp*128,+128) ----
        {
            const float* xcol = x + (size_t)(c0 + blo_kh * 16) * NP + bp * 128 + blo_p;
            float v[16];
#pragma unroll
            for (int k = 0; k < 16; k++) v[k] = xcol[(size_t)k * NP];
            uint32_t hw[8], lw[8];
#pragma unroll
            for (int i = 0; i < 8; i++) {
                unsigned short h0, l0, h1, l1;
                bf16_split(v[2*i],   h0, l0);
                bf16_split(v[2*i+1], h1, l1);
                hw[i] = (uint32_t)h0 | ((uint32_t)h1 << 16);
                lw[i] = (uint32_t)l0 | ((uint32_t)l1 << 16);
            }
            uint32_t base = blo_p * ROWB + blo_kh * 32;
            *(uint4*)(sBhi + base)      = make_uint4(hw[0], hw[1], hw[2], hw[3]);
            *(uint4*)(sBhi + base + 16) = make_uint4(hw[4], hw[5], hw[6], hw[7]);
            *(uint4*)(sBlo + base)      = make_uint4(lw[0], lw[1], lw[2], lw[3]);
            *(uint4*)(sBlo + base + 16) = make_uint4(lw[4], lw[5], lw[6], lw[7]);
        }
        __syncthreads();

        // ---- 2 k-steps of 16 within the chunk ----
#pragma unroll
        for (int ks = 0; ks < 2; ks++) {
            const int klb = ks * 32;     // byte offset of k-step within row

            uint32_t ahi[4][4], alo_[4][4];
#pragma unroll
            for (int i = 0; i < 4; i++) {
                uint32_t ao = aBaseOff + klb + (uint32_t)i * 16 * ROWA;
                ldsm_x4(ahi[i][0], ahi[i][1], ahi[i][2], ahi[i][3], sAhi_b + ao);
                ldsm_x4(alo_[i][0], alo_[i][1], alo_[i][2], alo_[i][3], sAlo_b + ao);
            }
#pragma unroll
            for (int j = 0; j < 4; j++) {
                uint32_t bo_ = bBaseOff + klb + (uint32_t)j * 8 * ROWB;
                uint32_t bh0, bh1, bl0, bl1;
                ldsm_x2(bh0, bh1, sBhi_b + bo_);
                ldsm_x2(bl0, bl1, sBlo_b + bo_);
#pragma unroll
                for (int i = 0; i < 4; i++) {
                    mma16816(acc[i][j], ahi[i][0], ahi[i][1], ahi[i][2], ahi[i][3], bh0, bh1);
                    mma16816(acc[i][j], ahi[i][0], ahi[i][1], ahi[i][2], ahi[i][3], bl0, bl1);
                    mma16816(acc[i][j], alo_[i][0], alo_[i][1], alo_[i][2], alo_[i][3], bh0, bh1);
                }
            }
        }
        __syncthreads();
    }

    // ---- epilogue: D element (row g/g+8, col 2q/2q+1) per subtile ----
    const int g = lane >> 2;
    const int q = lane & 3;
#pragma unroll
    for (int i = 0; i < 4; i++) {
        int o = bo * 128 + warp_m * 64 + i * 16 + g;
#pragma unroll
        for (int j = 0; j < 4; j++) {
            int p = bp * 128 + warp_n * 32 + j * 8 + 2 * q;
            *(float2*)(g_qkv + (size_t)o * NP + p)       = make_float2(acc[i][j][0], acc[i][j][1]);
            *(float2*)(g_qkv + (size_t)(o + 8) * NP + p) = make_float2(acc[i][j][2], acc[i][j][3]);
        }
    }
}

// ---------------------------------------------------------------------------
// Kernel 2: per-pixel per-head q.k score:  t[head][p] = (sum_d q*k) / 16
// Vectorized: 4 pixels per thread. grid (36, 8), 256 thr.
// ---------------------------------------------------------------------------
__global__ __launch_bounds__(256) void qk_dot()
{
    const int p4   = blockIdx.x * 256 + threadIdx.x;   // float4 index, < 9216
    const int head = blockIdx.y;
    const float4* qp = (const float4*)(g_qkv + (size_t)(head * 32) * NP) + p4;
    const float4* kp = (const float4*)(g_qkv + (size_t)(256 + head * 32) * NP) + p4;
    float4 s = make_float4(0.f, 0.f, 0.f, 0.f);
#pragma unroll
    for (int d = 0; d < 32; d++) {
        float4 q = qp[(size_t)d * (NP / 4)];
        float4 k = kp[(size_t)d * (NP / 4)];
        s.x += q.x * k.x; s.y += q.y * k.y; s.z += q.z * k.z; s.w += q.w * k.w;
    }
    s.x *= 0.0625f; s.y *= 0.0625f; s.z *= 0.0625f; s.w *= 0.0625f;
    ((float4*)(g_t + (size_t)head * NP))[p4] = s;
}

// ---------------------------------------------------------------------------
// Kernel 3: 3x3 regional softmax + weighted V sum.
// Block = (row h) x (head-group of 2 heads = 64 ch). 192 threads.
// Phase 1: softmax weights for 2 heads x 192 pixels into smem.
// Phase 2: thread = (w-quad 0..47, ch-sub 0..3); weights in 36 regs per head;
//          V rows loaded as float4 + 2 edge scalars (9 LDG / 4 outputs).
// OOB slots contribute score 0 (exp(0-m)) to the softmax (zero padding makes
// qk = 0, not -inf); OOB v contributes 0.
// ---------------------------------------------------------------------------
__global__ __launch_bounds__(192) void attn(float* __restrict__ out)
{
    __shared__ float w9s[2][9][192];   // [head_local][slot][w]

    const int h   = blockIdx.x;        // 0..191
    const int hg  = blockIdx.y;        // 0..3 head group
    const int tid = threadIdx.x;       // 0..191

    // ---- phase 1: softmax weights (each thread: w=tid, both heads) ----
    {
        const int w = tid;
#pragma unroll
        for (int hl = 0; hl < 2; hl++) {
            const int head = hg * 2 + hl;
            const float* tb = g_t + (size_t)head * NP;
            float sc[9];
#pragma unroll
            for (int s = 0; s < 9; s++) {
                int hh = h + s / 3 - 1;
                int ww = w + s % 3 - 1;
                float v = 0.f;
                if ((unsigned)hh < 192u && (unsigned)ww < 192u)
                    v = tb[hh * WW + ww];
                sc[s] = v;
            }
            float m = sc[0];
#pragma unroll
            for (int s = 1; s < 9; s++) m = fmaxf(m, sc[s]);
            float sum = 0.f;
#pragma unroll
            for (int s = 0; s < 9; s++) { float e = __expf(sc[s] - m); sc[s] = e; sum += e; }
            float inv = 1.0f / sum;
#pragma unroll
            for (int s = 0; s < 9; s++) w9s[hl][s][w] = sc[s] * inv;
        }
    }
    __syncthreads();

    // ---- phase 2 ----
    const int w0  = (tid % 48) * 4;    // output quad start
    const int cl4 = tid / 48;          // 0..3 channel-within-iter

    float4 Wt[3][3];                   // [dh][dw] weights for 4 outputs

    for (int co = 0; co < 16; co++) {  // 4 channels per iter
        if (co == 0 || co == 8) {
            const int hl = co >> 3;
#pragma unroll
            for (int s = 0; s < 9; s++)
                Wt[s / 3][s % 3] = *(const float4*)&w9s[hl][s][w0];
        }
        const int ch = hg * 64 + co * 4 + cl4;
        const float* vb = g_qkv + (size_t)(512 + ch) * NP;

        float o0 = 0.f, o1 = 0.f, o2 = 0.f, o3 = 0.f;
#pragma unroll
        for (int dh = 0; dh < 3; dh++) {
            int hh = h + dh - 1;
            if ((unsigned)hh >= 192u) continue;
            const float* row = vb + hh * WW;
            float4 c = *(const float4*)(row + w0);
            float left  = (w0 > 0)   ? row[w0 - 1] : 0.f;
            float right = (w0 < 188) ? row[w0 + 4] : 0.f;
            o0 += Wt[dh][0].x * left + Wt[dh][1].x * c.x + Wt[dh][2].x * c.y;
            o1 += Wt[dh][0].y * c.x  + Wt[dh][1].y * c.y + Wt[dh][2].y * c.z;
            o2 += Wt[dh][0].z * c.y  + Wt[dh][1].z * c.z + Wt[dh][2].z * c.w;
            o3 += Wt[dh][0].w * c.z  + Wt[dh][1].w * c.w + Wt[dh][2].w * right;
        }
        *(float4*)(out + (size_t)ch * NP + h * WW + w0) = make_float4(o0, o1, o2, o3);
    }
}

// ---------------------------------------------------------------------------
extern "C" void kernel_launch(void* const* d_in, const int* in_sizes, int n_in,
                              void* d_out, int out_size)
{
    const float* x  = (const float*)d_in[0];
    const float* wq = (const float*)d_in[1];
    const float* wk = (const float*)d_in[2];
    const float* wv = (const float*)d_in[3];
    float* out = (float*)d_out;

    dim3 g1(NP / 128, OC / 128);     // (288, 6)
    gemm_qkv<<<g1, 256>>>(x, wq, wk, wv);

    dim3 g2(NP / (256 * 4), NHEAD);  // (36, 8)
    qk_dot<<<g2, 256>>>();

    dim3 g3(HH, 4);                  // (192, 4)
    attn<<<g3, 192>>>(out);
}

// round 6
// speedup vs baseline: 2.1373x; 1.0362x over previous
#include <cuda_runtime.h>
#include <cuda_bf16.h>
#include <cstdint>

// Problem constants
#define C_IN   128
#define OC     768            // 256 q + 256 k + 256 v stacked
#define NP     36864          // 192*192 pixels
#define HH     192
#define WW     192
#define NHEAD  8

// Scratch
__device__ float g_qkv[(size_t)OC * NP];     // q [0,256), k [256,512), v [512,768) ; [ch][pixel]
__device__ float g_t[(size_t)NHEAD * NP];
__device__ __align__(16) unsigned short gWhi[(size_t)OC * C_IN];   // bf16 bits, [o][c]
__device__ __align__(16) unsigned short gWlo[(size_t)OC * C_IN];
__device__ __align__(16) unsigned short gXhi[(size_t)NP * C_IN];   // bf16 bits, [p][c]
__device__ __align__(16) unsigned short gXlo[(size_t)NP * C_IN];

// ---------------------------------------------------------------------------
__device__ __forceinline__ void bf16_split(float f, unsigned short& h, unsigned short& l)
{
    __nv_bfloat16 hb = __float2bfloat16(f);
    float r = f - __bfloat162float(hb);
    __nv_bfloat16 lb = __float2bfloat16(r);
    h = __bfloat16_as_ushort(hb);
    l = __bfloat16_as_ushort(lb);
}

__device__ __forceinline__ void mma16816(float c[4],
                                         uint32_t a0, uint32_t a1, uint32_t a2, uint32_t a3,
                                         uint32_t b0, uint32_t b1)
{
    asm volatile(
        "mma.sync.aligned.m16n8k16.row.col.f32.bf16.bf16.f32 "
        "{%0,%1,%2,%3}, {%4,%5,%6,%7}, {%8,%9}, {%0,%1,%2,%3};\n"
        : "+f"(c[0]), "+f"(c[1]), "+f"(c[2]), "+f"(c[3])
        : "r"(a0), "r"(a1), "r"(a2), "r"(a3), "r"(b0), "r"(b1));
}

__device__ __forceinline__ void ldsm_x4(uint32_t& r0, uint32_t& r1, uint32_t& r2, uint32_t& r3,
                                        uint32_t saddr)
{
    asm volatile("ldmatrix.sync.aligned.m8n8.x4.shared.b16 {%0,%1,%2,%3}, [%4];"
                 : "=r"(r0), "=r"(r1), "=r"(r2), "=r"(r3) : "r"(saddr));
}

__device__ __forceinline__ void ldsm_x2(uint32_t& r0, uint32_t& r1, uint32_t saddr)
{
    asm volatile("ldmatrix.sync.aligned.m8n8.x2.shared.b16 {%0,%1}, [%2];"
                 : "=r"(r0), "=r"(r1) : "r"(saddr));
}

__device__ __forceinline__ void cpa16(uint32_t saddr, const void* g)
{
    asm volatile("cp.async.cg.shared.global [%0], [%1], 16;" :: "r"(saddr), "l"(g));
}

// ---------------------------------------------------------------------------
// Pre-pass A: convert W (wq|wk|wv stacked) to bf16 hi/lo.  grid 96 x 256.
// ---------------------------------------------------------------------------
__global__ __launch_bounds__(256) void conv_w(
    const float* __restrict__ wq, const float* __restrict__ wk, const float* __restrict__ wv)
{
    int idx = (blockIdx.x * 256 + threadIdx.x) * 4;
    int row = idx >> 7, col = idx & 127;
    const float* src = (row < 256) ? (wq + (size_t)row * 128)
                     : (row < 512) ? (wk + (size_t)(row - 256) * 128)
                                   : (wv + (size_t)(row - 512) * 128);
    float4 v = *(const float4*)(src + col);
    unsigned short h[4], l[4];
    bf16_split(v.x, h[0], l[0]); bf16_split(v.y, h[1], l[1]);
    bf16_split(v.z, h[2], l[2]); bf16_split(v.w, h[3], l[3]);
    uint2 hw = make_uint2((uint32_t)h[0] | ((uint32_t)h[1] << 16),
                          (uint32_t)h[2] | ((uint32_t)h[3] << 16));
    uint2 lw = make_uint2((uint32_t)l[0] | ((uint32_t)l[1] << 16),
                          (uint32_t)l[2] | ((uint32_t)l[3] << 16));
    *(uint2*)(gWhi + idx) = hw;
    *(uint2*)(gWlo + idx) = lw;
}

// ---------------------------------------------------------------------------
// Pre-pass B: transpose+convert x [c][p] -> gX[p][c] bf16 hi/lo.
// Tile 32 pixels x 128 channels; grid 1152 x 256.
// ---------------------------------------------------------------------------
__global__ __launch_bounds__(256) void conv_x(const float* __restrict__ x)
{
    __shared__ float s[128][33];
    const int p0  = blockIdx.x * 32;
    const int tid = threadIdx.x;
    const int pr  = tid & 31, cr = tid >> 5;
#pragma unroll
    for (int l = 0; l < 16; l++) {
        int c = cr + l * 8;
        s[c][pr] = x[(size_t)c * NP + p0 + pr];
    }
    __syncthreads();
    const int p = tid >> 3, kq = tid & 7;
    __align__(16) unsigned short hv[16], lv[16];
#pragma unroll
    for (int i = 0; i < 16; i++)
        bf16_split(s[kq * 16 + i][p], hv[i], lv[i]);
    size_t base = (size_t)(p0 + p) * 128 + kq * 16;
    *(uint4*)(gXhi + base)     = ((const uint4*)hv)[0];
    *(uint4*)(gXhi + base + 8) = ((const uint4*)hv)[1];
    *(uint4*)(gXlo + base)     = ((const uint4*)lv)[0];
    *(uint4*)(gXlo + base + 8) = ((const uint4*)lv)[1];
}

// ---------------------------------------------------------------------------
// Kernel 1: QKV projection GEMM, tensor cores, cp.async double-buffered.
// CTA 128(o) x 128(p), K in 4 chunks of 32. Dynamic smem 80 KB:
// stage s: Ahi +0, Alo +10240, Bhi +20480, Blo +30720 (row stride 80 B, 64 B data).
// ---------------------------------------------------------------------------
#define ROWS   80
#define ASTAGE 40960

__global__ __launch_bounds__(256, 2) void gemm_qkv()
{
    extern __shared__ unsigned char dsm[];
    const uint32_t sbase = (uint32_t)__cvta_generic_to_shared(dsm);

    const int bp   = blockIdx.x;
    const int bo   = blockIdx.y;
    const int tid  = threadIdx.x;
    const int wid  = tid >> 5;
    const int lane = tid & 31;
    const int warp_m = wid >> 2;
    const int warp_n = wid & 3;

    // loader roles: per array, 2 chunks of 16B per thread
    const int lrow0 = tid >> 2, lseg0 = tid & 3;            // ids 0..255
    const int lrow1 = (tid + 256) >> 2, lseg1 = tid & 3;    // ids 256..511

    // ldmatrix lane roles
    const int a_mat  = lane >> 3;
    const int a_rowl = ((a_mat & 1) << 3) + (lane & 7);
    const int a_seg  = a_mat >> 1;
    const uint32_t aOff = (uint32_t)(warp_m * 64 + a_rowl) * ROWS + a_seg * 16;
    const int b_rowl = lane & 7;
    const int b_seg  = (lane >> 3) & 1;
    const uint32_t bOff = (uint32_t)(warp_n * 32 + b_rowl) * ROWS + b_seg * 16;

    const unsigned short* gA = gWhi;   // bases; hi/lo arrays are parallel
    const unsigned short* gAl = gWlo;
    const unsigned short* gB = gXhi;
    const unsigned short* gBl = gXlo;

    float acc[4][4][4];
#pragma unroll
    for (int i = 0; i < 4; i++)
#pragma unroll
        for (int j = 0; j < 4; j++)
#pragma unroll
            for (int r = 0; r < 4; r++) acc[i][j][r] = 0.f;

    // ---- issue chunk kc into stage st ----
    auto issue = [&](int kc, int st) {
        const uint32_t s0 = sbase + st * ASTAGE;
        // A rows: global o = bo*128 + row, bytes (o*128 + kc*32)*2 + seg*16
        {
            size_t gb0 = ((size_t)(bo * 128 + lrow0) * 128 + kc * 32);
            size_t gb1 = ((size_t)(bo * 128 + lrow1) * 128 + kc * 32);
            cpa16(s0 + lrow0 * ROWS + lseg0 * 16,         gA  + gb0 + lseg0 * 8);
            cpa16(s0 + lrow1 * ROWS + lseg1 * 16,         gA  + gb1 + lseg1 * 8);
            cpa16(s0 + 10240 + lrow0 * ROWS + lseg0 * 16, gAl + gb0 + lseg0 * 8);
            cpa16(s0 + 10240 + lrow1 * ROWS + lseg1 * 16, gAl + gb1 + lseg1 * 8);
        }
        {
            size_t gb0 = ((size_t)(bp * 128 + lrow0) * 128 + kc * 32);
            size_t gb1 = ((size_t)(bp * 128 + lrow1) * 128 + kc * 32);
            cpa16(s0 + 20480 + lrow0 * ROWS + lseg0 * 16, gB  + gb0 + lseg0 * 8);
            cpa16(s0 + 20480 + lrow1 * ROWS + lseg1 * 16, gB  + gb1 + lseg1 * 8);
            cpa16(s0 + 30720 + lrow0 * ROWS + lseg0 * 16, gBl + gb0 + lseg0 * 8);
            cpa16(s0 + 30720 + lrow1 * ROWS + lseg1 * 16, gBl + gb1 + lseg1 * 8);
        }
    };

    issue(0, 0);
    asm volatile("cp.async.commit_group;");

    for (int kc = 0; kc < 4; kc++) {
        const int st = kc & 1;
        if (kc < 3) issue(kc + 1, st ^ 1);
        asm volatile("cp.async.commit_group;");
        if (kc < 3) asm volatile("cp.async.wait_group 1;");
        else        asm volatile("cp.async.wait_group 0;");
        __syncthreads();

        const uint32_t sAhi_b = sbase + st * ASTAGE;
        const uint32_t sAlo_b = sAhi_b + 10240;
        const uint32_t sBhi_b = sAhi_b + 20480;
        const uint32_t sBlo_b = sAhi_b + 30720;

#pragma unroll
        for (int ks = 0; ks < 2; ks++) {
            const int klb = ks * 32;
            uint32_t ahi[4][4], alo_[4][4];
#pragma unroll
            for (int i = 0; i < 4; i++) {
                uint32_t ao = aOff + klb + (uint32_t)i * 16 * ROWS;
                ldsm_x4(ahi[i][0], ahi[i][1], ahi[i][2], ahi[i][3], sAhi_b + ao);
                ldsm_x4(alo_[i][0], alo_[i][1], alo_[i][2], alo_[i][3], sAlo_b + ao);
            }
#pragma unroll
            for (int j = 0; j < 4; j++) {
                uint32_t bo_ = bOff + klb + (uint32_t)j * 8 * ROWS;
                uint32_t bh0, bh1, bl0, bl1;
                ldsm_x2(bh0, bh1, sBhi_b + bo_);
                ldsm_x2(bl0, bl1, sBlo_b + bo_);
#pragma unroll
                for (int i = 0; i < 4; i++) {
                    mma16816(acc[i][j], ahi[i][0], ahi[i][1], ahi[i][2], ahi[i][3], bh0, bh1);
                    mma16816(acc[i][j], ahi[i][0], ahi[i][1], ahi[i][2], ahi[i][3], bl0, bl1);
                    mma16816(acc[i][j], alo_[i][0], alo_[i][1], alo_[i][2], alo_[i][3], bh0, bh1);
                }
            }
        }
        __syncthreads();
    }

    // ---- epilogue ----
    const int g = lane >> 2;
    const int q = lane & 3;
#pragma unroll
    for (int i = 0; i < 4; i++) {
        int o = bo * 128 + warp_m * 64 + i * 16 + g;
#pragma unroll
        for (int j = 0; j < 4; j++) {
            int p = bp * 128 + warp_n * 32 + j * 8 + 2 * q;
            *(float2*)(g_qkv + (size_t)o * NP + p)       = make_float2(acc[i][j][0], acc[i][j][1]);
            *(float2*)(g_qkv + (size_t)(o + 8) * NP + p) = make_float2(acc[i][j][2], acc[i][j][3]);
        }
    }
}

// ---------------------------------------------------------------------------
// Kernel 2: per-pixel per-head q.k score:  t[head][p] = (sum_d q*k) / 16
// 8 pixels/thread (2 independent float4 chains). grid (18, 8), 256 thr.
// ---------------------------------------------------------------------------
__global__ __launch_bounds__(256) void qk_dot()
{
    const int p8   = blockIdx.x * 256 + threadIdx.x;   // 0..4607
    const int head = blockIdx.y;
    const float4* qp = (const float4*)(g_qkv + (size_t)(head * 32) * NP) + p8 * 2;
    const float4* kp = (const float4*)(g_qkv + (size_t)(256 + head * 32) * NP) + p8 * 2;
    float4 s0 = make_float4(0.f, 0.f, 0.f, 0.f);
    float4 s1 = make_float4(0.f, 0.f, 0.f, 0.f);
#pragma unroll
    for (int d = 0; d < 32; d++) {
        float4 q0 = qp[(size_t)d * (NP / 4)];
        float4 k0 = kp[(size_t)d * (NP / 4)];
        float4 q1 = qp[(size_t)d * (NP / 4) + 1];
        float4 k1 = kp[(size_t)d * (NP / 4) + 1];
        s0.x += q0.x * k0.x; s0.y += q0.y * k0.y; s0.z += q0.z * k0.z; s0.w += q0.w * k0.w;
        s1.x += q1.x * k1.x; s1.y += q1.y * k1.y; s1.z += q1.z * k1.z; s1.w += q1.w * k1.w;
    }
    const float iv = 0.0625f;
    s0.x *= iv; s0.y *= iv; s0.z *= iv; s0.w *= iv;
    s1.x *= iv; s1.y *= iv; s1.z *= iv; s1.w *= iv;
    float4* tb = (float4*)(g_t + (size_t)head * NP) + p8 * 2;
    tb[0] = s0; tb[1] = s1;
}

// ---------------------------------------------------------------------------
// Kernel 3: 3x3 regional softmax + weighted V sum.
// OOB slots contribute score 0 (exp(0-m)); OOB v contributes 0.
// ---------------------------------------------------------------------------
__global__ __launch_bounds__(192) void attn(float* __restrict__ out)
{
    __shared__ float w9s[2][9][192];

    const int h   = blockIdx.x;
    const int hg  = blockIdx.y;
    const int tid = threadIdx.x;

    {
        const int w = tid;
#pragma unroll
        for (int hl = 0; hl < 2; hl++) {
            const int head = hg * 2 + hl;
            const float* tb = g_t + (size_t)head * NP;
            float sc[9];
#pragma unroll
            for (int s = 0; s < 9; s++) {
                int hh = h + s / 3 - 1;
                int ww = w + s % 3 - 1;
                float v = 0.f;
                if ((unsigned)hh < 192u && (unsigned)ww < 192u)
                    v = tb[hh * WW + ww];
                sc[s] = v;
            }
            float m = sc[0];
#pragma unroll
            for (int s = 1; s < 9; s++) m = fmaxf(m, sc[s]);
            float sum = 0.f;
#pragma unroll
            for (int s = 0; s < 9; s++) { float e = __expf(sc[s] - m); sc[s] = e; sum += e; }
            float inv = 1.0f / sum;
#pragma unroll
            for (int s = 0; s < 9; s++) w9s[hl][s][w] = sc[s] * inv;
        }
    }
    __syncthreads();

    const int w0  = (tid % 48) * 4;
    const int cl4 = tid / 48;

    float4 Wt[3][3];

    for (int co = 0; co < 16; co++) {
        if (co == 0 || co == 8) {
            const int hl = co >> 3;
#pragma unroll
            for (int s = 0; s < 9; s++)
                Wt[s / 3][s % 3] = *(const float4*)&w9s[hl][s][w0];
        }
        const int ch = hg * 64 + co * 4 + cl4;
        const float* vb = g_qkv + (size_t)(512 + ch) * NP;

        float o0 = 0.f, o1 = 0.f, o2 = 0.f, o3 = 0.f;
#pragma unroll
        for (int dh = 0; dh < 3; dh++) {
            int hh = h + dh - 1;
            if ((unsigned)hh >= 192u) continue;
            const float* row = vb + hh * WW;
            float4 c = *(const float4*)(row + w0);
            float left  = (w0 > 0)   ? row[w0 - 1] : 0.f;
            float right = (w0 < 188) ? row[w0 + 4] : 0.f;
            o0 += Wt[dh][0].x * left + Wt[dh][1].x * c.x + Wt[dh][2].x * c.y;
            o1 += Wt[dh][0].y * c.x  + Wt[dh][1].y * c.y + Wt[dh][2].y * c.z;
            o2 += Wt[dh][0].z * c.y  + Wt[dh][1].z * c.z + Wt[dh][2].z * c.w;
            o3 += Wt[dh][0].w * c.z  + Wt[dh][1].w * c.w + Wt[dh][2].w * right;
        }
        *(float4*)(out + (size_t)ch * NP + h * WW + w0) = make_float4(o0, o1, o2, o3);
    }
}

// ---------------------------------------------------------------------------
extern "C" void kernel_launch(void* const* d_in, const int* in_sizes, int n_in,
                              void* d_out, int out_size)
{
    const float* x  = (const float*)d_in[0];
    const float* wq = (const float*)d_in[1];
    const float* wk = (const float*)d_in[2];
    const float* wv = (const float*)d_in[3];
    float* out = (float*)d_out;

    cudaFuncSetAttribute(gemm_qkv, cudaFuncAttributeMaxDynamicSharedMemorySize, 2 * ASTAGE);

    conv_w<<<96, 256>>>(wq, wk, wv);
    conv_x<<<NP / 32, 256>>>(x);

    dim3 g1(NP / 128, OC / 128);     // (288, 6)
    gemm_qkv<<<g1, 256, 2 * ASTAGE>>>();

    dim3 g2(NP / (256 * 8), NHEAD);  // (18, 8)
    qk_dot<<<g2, 256>>>();

    dim3 g3(HH, 4);                  // (192, 4)
    attn<<<g3, 192>>>(out);
}

// round 7
// speedup vs baseline: 2.8340x; 1.3260x over previous
#include <cuda_runtime.h>
#include <cuda_bf16.h>
#include <cstdint>

// Problem constants
#define C_IN   128
#define OC     768            // 512 qk-interleaved + 256 v
#define NP     36864          // 192*192 pixels
#define HH     192
#define WW     192
#define NHEAD  8

// Scratch
__device__ float g_v[(size_t)256 * NP];      // v [ch][pixel]
__device__ float g_t[(size_t)NHEAD * NP];    // scores
__device__ __align__(16) unsigned short gWhi[(size_t)OC * C_IN];   // bf16 bits, [o][c], head-interleaved qk
__device__ __align__(16) unsigned short gWlo[(size_t)OC * C_IN];
__device__ __align__(16) unsigned short gXhi[(size_t)NP * C_IN];   // bf16 bits, [p][c]
__device__ __align__(16) unsigned short gXlo[(size_t)NP * C_IN];

// ---------------------------------------------------------------------------
__device__ __forceinline__ void bf16_split(float f, unsigned short& h, unsigned short& l)
{
    __nv_bfloat16 hb = __float2bfloat16(f);
    float r = f - __bfloat162float(hb);
    __nv_bfloat16 lb = __float2bfloat16(r);
    h = __bfloat16_as_ushort(hb);
    l = __bfloat16_as_ushort(lb);
}

__device__ __forceinline__ void mma16816(float c[4],
                                         uint32_t a0, uint32_t a1, uint32_t a2, uint32_t a3,
                                         uint32_t b0, uint32_t b1)
{
    asm volatile(
        "mma.sync.aligned.m16n8k16.row.col.f32.bf16.bf16.f32 "
        "{%0,%1,%2,%3}, {%4,%5,%6,%7}, {%8,%9}, {%0,%1,%2,%3};\n"
        : "+f"(c[0]), "+f"(c[1]), "+f"(c[2]), "+f"(c[3])
        : "r"(a0), "r"(a1), "r"(a2), "r"(a3), "r"(b0), "r"(b1));
}

__device__ __forceinline__ void ldsm_x4(uint32_t& r0, uint32_t& r1, uint32_t& r2, uint32_t& r3,
                                        uint32_t saddr)
{
    asm volatile("ldmatrix.sync.aligned.m8n8.x4.shared.b16 {%0,%1,%2,%3}, [%4];"
                 : "=r"(r0), "=r"(r1), "=r"(r2), "=r"(r3) : "r"(saddr));
}

__device__ __forceinline__ void ldsm_x2(uint32_t& r0, uint32_t& r1, uint32_t saddr)
{
    asm volatile("ldmatrix.sync.aligned.m8n8.x2.shared.b16 {%0,%1}, [%2];"
                 : "=r"(r0), "=r"(r1) : "r"(saddr));
}

__device__ __forceinline__ void cpa16(uint32_t saddr, const void* g)
{
    asm volatile("cp.async.cg.shared.global [%0], [%1], 16;" :: "r"(saddr), "l"(g));
}

// ---------------------------------------------------------------------------
// Pre-pass A: convert W to bf16 hi/lo with head-interleaved q/k layout:
// rows [0,512): block of 64 per head = [wq head rows 0..31 | wk head rows 0..31]
// rows [512,768): wv. grid 96 x 256.
// ---------------------------------------------------------------------------
__global__ __launch_bounds__(256) void conv_w(
    const float* __restrict__ wq, const float* __restrict__ wk, const float* __restrict__ wv)
{
    int idx = (blockIdx.x * 256 + threadIdx.x) * 4;
    int row = idx >> 7, col = idx & 127;
    const float* src;
    if (row < 512) {
        int head = row >> 6, sub = row & 63;
        src = (sub < 32) ? (wq + (size_t)(head * 32 + sub) * 128)
                         : (wk + (size_t)(head * 32 + sub - 32) * 128);
    } else {
        src = wv + (size_t)(row - 512) * 128;
    }
    float4 v = *(const float4*)(src + col);
    unsigned short h[4], l[4];
    bf16_split(v.x, h[0], l[0]); bf16_split(v.y, h[1], l[1]);
    bf16_split(v.z, h[2], l[2]); bf16_split(v.w, h[3], l[3]);
    *(uint2*)(gWhi + idx) = make_uint2((uint32_t)h[0] | ((uint32_t)h[1] << 16),
                                       (uint32_t)h[2] | ((uint32_t)h[3] << 16));
    *(uint2*)(gWlo + idx) = make_uint2((uint32_t)l[0] | ((uint32_t)l[1] << 16),
                                       (uint32_t)l[2] | ((uint32_t)l[3] << 16));
}

// ---------------------------------------------------------------------------
// Pre-pass B: transpose+convert x [c][p] -> gX[p][c] bf16 hi/lo.
// ---------------------------------------------------------------------------
__global__ __launch_bounds__(256) void conv_x(const float* __restrict__ x)
{
    __shared__ float s[128][33];
    const int p0  = blockIdx.x * 32;
    const int tid = threadIdx.x;
    const int pr  = tid & 31, cr = tid >> 5;
#pragma unroll
    for (int l = 0; l < 16; l++) {
        int c = cr + l * 8;
        s[c][pr] = x[(size_t)c * NP + p0 + pr];
    }
    __syncthreads();
    const int p = tid >> 3, kq = tid & 7;
    __align__(16) unsigned short hv[16], lv[16];
#pragma unroll
    for (int i = 0; i < 16; i++)
        bf16_split(s[kq * 16 + i][p], hv[i], lv[i]);
    size_t base = (size_t)(p0 + p) * 128 + kq * 16;
    *(uint4*)(gXhi + base)     = ((const uint4*)hv)[0];
    *(uint4*)(gXhi + base + 8) = ((const uint4*)hv)[1];
    *(uint4*)(gXlo + base)     = ((const uint4*)lv)[0];
    *(uint4*)(gXlo + base + 8) = ((const uint4*)lv)[1];
}

// ---------------------------------------------------------------------------
// Kernel 1: QKV projection GEMM + fused q.k epilogue.
// CTA 128(o) x 128(p). bo<4: q/k heads (2 per CTA) -> write t only.
// bo in {4,5}: v -> write g_v. Double-buffered cp.async, smem 80 KB.
// ---------------------------------------------------------------------------
#define ROWS   80
#define ASTAGE 40960

__global__ __launch_bounds__(256, 2) void gemm_qkv()
{
    extern __shared__ unsigned char dsm[];
    const uint32_t sbase = (uint32_t)__cvta_generic_to_shared(dsm);

    const int bp   = blockIdx.x;
    const int bo   = blockIdx.y;
    const int tid  = threadIdx.x;
    const int wid  = tid >> 5;
    const int lane = tid & 31;
    const int warp_m = wid >> 2;
    const int warp_n = wid & 3;

    const int lrow0 = tid >> 2, lseg0 = tid & 3;
    const int lrow1 = (tid + 256) >> 2, lseg1 = tid & 3;

    const int a_mat  = lane >> 3;
    const int a_rowl = ((a_mat & 1) << 3) + (lane & 7);
    const int a_seg  = a_mat >> 1;
    const uint32_t aOff = (uint32_t)(warp_m * 64 + a_rowl) * ROWS + a_seg * 16;
    const int b_rowl = lane & 7;
    const int b_seg  = (lane >> 3) & 1;
    const uint32_t bOff = (uint32_t)(warp_n * 32 + b_rowl) * ROWS + b_seg * 16;

    float acc[4][4][4];
#pragma unroll
    for (int i = 0; i < 4; i++)
#pragma unroll
        for (int j = 0; j < 4; j++)
#pragma unroll
            for (int r = 0; r < 4; r++) acc[i][j][r] = 0.f;

    auto issue = [&](int kc, int st) {
        const uint32_t s0 = sbase + st * ASTAGE;
        {
            size_t gb0 = ((size_t)(bo * 128 + lrow0) * 128 + kc * 32);
            size_t gb1 = ((size_t)(bo * 128 + lrow1) * 128 + kc * 32);
            cpa16(s0 + lrow0 * ROWS + lseg0 * 16,         gWhi + gb0 + lseg0 * 8);
            cpa16(s0 + lrow1 * ROWS + lseg1 * 16,         gWhi + gb1 + lseg1 * 8);
            cpa16(s0 + 10240 + lrow0 * ROWS + lseg0 * 16, gWlo + gb0 + lseg0 * 8);
            cpa16(s0 + 10240 + lrow1 * ROWS + lseg1 * 16, gWlo + gb1 + lseg1 * 8);
        }
        {
            size_t gb0 = ((size_t)(bp * 128 + lrow0) * 128 + kc * 32);
            size_t gb1 = ((size_t)(bp * 128 + lrow1) * 128 + kc * 32);
            cpa16(s0 + 20480 + lrow0 * ROWS + lseg0 * 16, gXhi + gb0 + lseg0 * 8);
            cpa16(s0 + 20480 + lrow1 * ROWS + lseg1 * 16, gXhi + gb1 + lseg1 * 8);
            cpa16(s0 + 30720 + lrow0 * ROWS + lseg0 * 16, gXlo + gb0 + lseg0 * 8);
            cpa16(s0 + 30720 + lrow1 * ROWS + lseg1 * 16, gXlo + gb1 + lseg1 * 8);
        }
    };

    issue(0, 0);
    asm volatile("cp.async.commit_group;");

    for (int kc = 0; kc < 4; kc++) {
        const int st = kc & 1;
        if (kc < 3) issue(kc + 1, st ^ 1);
        asm volatile("cp.async.commit_group;");
        if (kc < 3) asm volatile("cp.async.wait_group 1;");
        else        asm volatile("cp.async.wait_group 0;");
        __syncthreads();

        const uint32_t sAhi_b = sbase + st * ASTAGE;
        const uint32_t sAlo_b = sAhi_b + 10240;
        const uint32_t sBhi_b = sAhi_b + 20480;
        const uint32_t sBlo_b = sAhi_b + 30720;

#pragma unroll
        for (int ks = 0; ks < 2; ks++) {
            const int klb = ks * 32;
            uint32_t ahi[4][4], alo_[4][4];
#pragma unroll
            for (int i = 0; i < 4; i++) {
                uint32_t ao = aOff + klb + (uint32_t)i * 16 * ROWS;
                ldsm_x4(ahi[i][0], ahi[i][1], ahi[i][2], ahi[i][3], sAhi_b + ao);
                ldsm_x4(alo_[i][0], alo_[i][1], alo_[i][2], alo_[i][3], sAlo_b + ao);
            }
#pragma unroll
            for (int j = 0; j < 4; j++) {
                uint32_t bo_ = bOff + klb + (uint32_t)j * 8 * ROWS;
                uint32_t bh0, bh1, bl0, bl1;
                ldsm_x2(bh0, bh1, sBhi_b + bo_);
                ldsm_x2(bl0, bl1, sBlo_b + bo_);
                // term-outer, i-inner: 4 independent accumulators between reuses
#pragma unroll
                for (int i = 0; i < 4; i++)
                    mma16816(acc[i][j], ahi[i][0], ahi[i][1], ahi[i][2], ahi[i][3], bh0, bh1);
#pragma unroll
                for (int i = 0; i < 4; i++)
                    mma16816(acc[i][j], ahi[i][0], ahi[i][1], ahi[i][2], ahi[i][3], bl0, bl1);
#pragma unroll
                for (int i = 0; i < 4; i++)
                    mma16816(acc[i][j], alo_[i][0], alo_[i][1], alo_[i][2], alo_[i][3], bh0, bh1);
            }
        }
        __syncthreads();
    }

    const int g = lane >> 2;
    const int q = lane & 3;

    if (bo < 4) {
        // ---- fused q.k epilogue: warp_m's 64 rows = [32 q | 32 k] of one head.
        // acc rows: i=0,1 -> q rows (i*16+g, +8); i=2,3 -> k rows (+32). Same cols.
        const int head = bo * 2 + warp_m;
        float* tb = g_t + (size_t)head * NP;
#pragma unroll
        for (int j = 0; j < 4; j++) {
            float s0 = 0.f, s1 = 0.f;
#pragma unroll
            for (int i = 0; i < 2; i++) {
                s0 += acc[i][j][0] * acc[i + 2][j][0] + acc[i][j][2] * acc[i + 2][j][2];
                s1 += acc[i][j][1] * acc[i + 2][j][1] + acc[i][j][3] * acc[i + 2][j][3];
            }
            // reduce over the 8 g-lanes (stride-4 lane groups)
#pragma unroll
            for (int m = 4; m <= 16; m <<= 1) {
                s0 += __shfl_xor_sync(0xffffffffu, s0, m);
                s1 += __shfl_xor_sync(0xffffffffu, s1, m);
            }
            if (g == 0) {
                int p = bp * 128 + warp_n * 32 + j * 8 + 2 * q;
                *(float2*)(tb + p) = make_float2(s0 * 0.0625f, s1 * 0.0625f);
            }
        }
    } else {
        // ---- v epilogue ----
#pragma unroll
        for (int i = 0; i < 4; i++) {
            int o = (bo - 4) * 128 + warp_m * 64 + i * 16 + g;
#pragma unroll
            for (int j = 0; j < 4; j++) {
                int p = bp * 128 + warp_n * 32 + j * 8 + 2 * q;
                *(float2*)(g_v + (size_t)o * NP + p)       = make_float2(acc[i][j][0], acc[i][j][1]);
                *(float2*)(g_v + (size_t)(o + 8) * NP + p) = make_float2(acc[i][j][2], acc[i][j][3]);
            }
        }
    }
}

// ---------------------------------------------------------------------------
// Kernel 3: 3x3 regional softmax + weighted V sum.
// OOB slots contribute score 0 (exp(0-m)); OOB v contributes 0.
// ---------------------------------------------------------------------------
__global__ __launch_bounds__(192) void attn(float* __restrict__ out)
{
    __shared__ float w9s[2][9][192];

    const int h   = blockIdx.x;
    const int hg  = blockIdx.y;
    const int tid = threadIdx.x;

    {
        const int w = tid;
#pragma unroll
        for (int hl = 0; hl < 2; hl++) {
            const int head = hg * 2 + hl;
            const float* tb = g_t + (size_t)head * NP;
            float sc[9];
#pragma unroll
            for (int s = 0; s < 9; s++) {
                int hh = h + s / 3 - 1;
                int ww = w + s % 3 - 1;
                float v = 0.f;
                if ((unsigned)hh < 192u && (unsigned)ww < 192u)
                    v = tb[hh * WW + ww];
                sc[s] = v;
            }
            float m = sc[0];
#pragma unroll
            for (int s = 1; s < 9; s++) m = fmaxf(m, sc[s]);
            float sum = 0.f;
#pragma unroll
            for (int s = 0; s < 9; s++) { float e = __expf(sc[s] - m); sc[s] = e; sum += e; }
            float inv = 1.0f / sum;
#pragma unroll
            for (int s = 0; s < 9; s++) w9s[hl][s][w] = sc[s] * inv;
        }
    }
    __syncthreads();

    const int w0  = (tid % 48) * 4;
    const int cl4 = tid / 48;

    float4 Wt[3][3];

    for (int co = 0; co < 16; co++) {
        if (co == 0 || co == 8) {
            const int hl = co >> 3;
#pragma unroll
            for (int s = 0; s < 9; s++)
                Wt[s / 3][s % 3] = *(const float4*)&w9s[hl][s][w0];
        }
        const int ch = hg * 64 + co * 4 + cl4;
        const float* vb = g_v + (size_t)ch * NP;

        float o0 = 0.f, o1 = 0.f, o2 = 0.f, o3 = 0.f;
#pragma unroll
        for (int dh = 0; dh < 3; dh++) {
            int hh = h + dh - 1;
            if ((unsigned)hh >= 192u) continue;
            const float* row = vb + hh * WW;
            float4 c = *(const float4*)(row + w0);
            float left  = (w0 > 0)   ? row[w0 - 1] : 0.f;
            float right = (w0 < 188) ? row[w0 + 4] : 0.f;
            o0 += Wt[dh][0].x * left + Wt[dh][1].x * c.x + Wt[dh][2].x * c.y;
            o1 += Wt[dh][0].y * c.x  + Wt[dh][1].y * c.y + Wt[dh][2].y * c.z;
            o2 += Wt[dh][0].z * c.y  + Wt[dh][1].z * c.z + Wt[dh][2].z * c.w;
            o3 += Wt[dh][0].w * c.z  + Wt[dh][1].w * c.w + Wt[dh][2].w * right;
        }
        *(float4*)(out + (size_t)ch * NP + h * WW + w0) = make_float4(o0, o1, o2, o3);
    }
}

// ---------------------------------------------------------------------------
extern "C" void kernel_launch(void* const* d_in, const int* in_sizes, int n_in,
                              void* d_out, int out_size)
{
    const float* x  = (const float*)d_in[0];
    const float* wq = (const float*)d_in[1];
    const float* wk = (const float*)d_in[2];
    const float* wv = (const float*)d_in[3];
    float* out = (float*)d_out;

    cudaFuncSetAttribute(gemm_qkv, cudaFuncAttributeMaxDynamicSharedMemorySize, 2 * ASTAGE);

    conv_w<<<96, 256>>>(wq, wk, wv);
    conv_x<<<NP / 32, 256>>>(x);

    dim3 g1(NP / 128, OC / 128);     // (288, 6)
    gemm_qkv<<<g1, 256, 2 * ASTAGE>>>();

    dim3 g3(HH, 4);                  // (192, 4)
    attn<<<g3, 192>>>(out);
}

// round 8
// speedup vs baseline: 2.9698x; 1.0479x over previous
#include <cuda_runtime.h>
#include <cuda_bf16.h>
#include <cstdint>

// Problem constants
#define C_IN   128
#define OC     768            // 512 qk-interleaved + 256 v
#define NP     36864          // 192*192 pixels
#define HH     192
#define WW     192
#define NHEAD  8

// Scratch
__device__ float g_v[(size_t)256 * NP];      // v [ch][pixel]
__device__ float g_t[(size_t)NHEAD * NP];    // scores
__device__ __align__(16) unsigned short gWhi[(size_t)OC * C_IN];   // bf16 bits, [o][c], head-interleaved qk
__device__ __align__(16) unsigned short gWlo[(size_t)OC * C_IN];
__device__ __align__(16) unsigned short gXhi[(size_t)NP * C_IN];   // bf16 bits, [p][c]
__device__ __align__(16) unsigned short gXlo[(size_t)NP * C_IN];

// ---------------------------------------------------------------------------
__device__ __forceinline__ void bf16_split(float f, unsigned short& h, unsigned short& l)
{
    __nv_bfloat16 hb = __float2bfloat16(f);
    float r = f - __bfloat162float(hb);
    __nv_bfloat16 lb = __float2bfloat16(r);
    h = __bfloat16_as_ushort(hb);
    l = __bfloat16_as_ushort(lb);
}

__device__ __forceinline__ void mma16816(float c[4],
                                         uint32_t a0, uint32_t a1, uint32_t a2, uint32_t a3,
                                         uint32_t b0, uint32_t b1)
{
    asm volatile(
        "mma.sync.aligned.m16n8k16.row.col.f32.bf16.bf16.f32 "
        "{%0,%1,%2,%3}, {%4,%5,%6,%7}, {%8,%9}, {%0,%1,%2,%3};\n"
        : "+f"(c[0]), "+f"(c[1]), "+f"(c[2]), "+f"(c[3])
        : "r"(a0), "r"(a1), "r"(a2), "r"(a3), "r"(b0), "r"(b1));
}

__device__ __forceinline__ void ldsm_x4(uint32_t& r0, uint32_t& r1, uint32_t& r2, uint32_t& r3,
                                        uint32_t saddr)
{
    asm volatile("ldmatrix.sync.aligned.m8n8.x4.shared.b16 {%0,%1,%2,%3}, [%4];"
                 : "=r"(r0), "=r"(r1), "=r"(r2), "=r"(r3) : "r"(saddr));
}

__device__ __forceinline__ void ldsm_x2(uint32_t& r0, uint32_t& r1, uint32_t saddr)
{
    asm volatile("ldmatrix.sync.aligned.m8n8.x2.shared.b16 {%0,%1}, [%2];"
                 : "=r"(r0), "=r"(r1) : "r"(saddr));
}

__device__ __forceinline__ void cpa16(uint32_t saddr, const void* g)
{
    asm volatile("cp.async.cg.shared.global [%0], [%1], 16;" :: "r"(saddr), "l"(g));
}

// ---------------------------------------------------------------------------
// Pre-pass A: convert W to bf16 hi/lo with head-interleaved q/k layout:
// rows [0,512): block of 64 per head = [wq head rows 0..31 | wk head rows 0..31]
// rows [512,768): wv. grid 96 x 256.
// ---------------------------------------------------------------------------
__global__ __launch_bounds__(256) void conv_w(
    const float* __restrict__ wq, const float* __restrict__ wk, const float* __restrict__ wv)
{
    int idx = (blockIdx.x * 256 + threadIdx.x) * 4;
    int row = idx >> 7, col = idx & 127;
    const float* src;
    if (row < 512) {
        int head = row >> 6, sub = row & 63;
        src = (sub < 32) ? (wq + (size_t)(head * 32 + sub) * 128)
                         : (wk + (size_t)(head * 32 + sub - 32) * 128);
    } else {
        src = wv + (size_t)(row - 512) * 128;
    }
    float4 v = *(const float4*)(src + col);
    unsigned short h[4], l[4];
    bf16_split(v.x, h[0], l[0]); bf16_split(v.y, h[1], l[1]);
    bf16_split(v.z, h[2], l[2]); bf16_split(v.w, h[3], l[3]);
    *(uint2*)(gWhi + idx) = make_uint2((uint32_t)h[0] | ((uint32_t)h[1] << 16),
                                       (uint32_t)h[2] | ((uint32_t)h[3] << 16));
    *(uint2*)(gWlo + idx) = make_uint2((uint32_t)l[0] | ((uint32_t)l[1] << 16),
                                       (uint32_t)l[2] | ((uint32_t)l[3] << 16));
}

// ---------------------------------------------------------------------------
// Pre-pass B: transpose+convert x [c][p] -> gX[p][c] bf16 hi/lo.
// ---------------------------------------------------------------------------
__global__ __launch_bounds__(256) void conv_x(const float* __restrict__ x)
{
    __shared__ float s[128][33];
    const int p0  = blockIdx.x * 32;
    const int tid = threadIdx.x;
    const int pr  = tid & 31, cr = tid >> 5;
#pragma unroll
    for (int l = 0; l < 16; l++) {
        int c = cr + l * 8;
        s[c][pr] = x[(size_t)c * NP + p0 + pr];
    }
    __syncthreads();
    const int p = tid >> 3, kq = tid & 7;
    __align__(16) unsigned short hv[16], lv[16];
#pragma unroll
    for (int i = 0; i < 16; i++)
        bf16_split(s[kq * 16 + i][p], hv[i], lv[i]);
    size_t base = (size_t)(p0 + p) * 128 + kq * 16;
    *(uint4*)(gXhi + base)     = ((const uint4*)hv)[0];
    *(uint4*)(gXhi + base + 8) = ((const uint4*)hv)[1];
    *(uint4*)(gXlo + base)     = ((const uint4*)lv)[0];
    *(uint4*)(gXlo + base + 8) = ((const uint4*)lv)[1];
}

// ---------------------------------------------------------------------------
// Kernel 1: QKV projection GEMM + fused q.k epilogue.
// CTA 128(o) x 128(p). bo<4: q/k heads (2 per CTA) -> write t only.
// bo in {4,5}: v -> write g_v. Double-buffered cp.async, smem 80 KB.
// ---------------------------------------------------------------------------
#define ROWS   80
#define ASTAGE 40960

__global__ __launch_bounds__(256, 2) void gemm_qkv()
{
    extern __shared__ unsigned char dsm[];
    const uint32_t sbase = (uint32_t)__cvta_generic_to_shared(dsm);

    const int bp   = blockIdx.x;
    const int bo   = blockIdx.y;
    const int tid  = threadIdx.x;
    const int wid  = tid >> 5;
    const int lane = tid & 31;
    const int warp_m = wid >> 2;
    const int warp_n = wid & 3;

    const int lrow0 = tid >> 2, lseg0 = tid & 3;
    const int lrow1 = (tid + 256) >> 2, lseg1 = tid & 3;

    const int a_mat  = lane >> 3;
    const int a_rowl = ((a_mat & 1) << 3) + (lane & 7);
    const int a_seg  = a_mat >> 1;
    const uint32_t aOff = (uint32_t)(warp_m * 64 + a_rowl) * ROWS + a_seg * 16;
    const int b_rowl = lane & 7;
    const int b_seg  = (lane >> 3) & 1;
    const uint32_t bOff = (uint32_t)(warp_n * 32 + b_rowl) * ROWS + b_seg * 16;

    float acc[4][4][4];
#pragma unroll
    for (int i = 0; i < 4; i++)
#pragma unroll
        for (int j = 0; j < 4; j++)
#pragma unroll
            for (int r = 0; r < 4; r++) acc[i][j][r] = 0.f;

    auto issue = [&](int kc, int st) {
        const uint32_t s0 = sbase + st * ASTAGE;
        {
            size_t gb0 = ((size_t)(bo * 128 + lrow0) * 128 + kc * 32);
            size_t gb1 = ((size_t)(bo * 128 + lrow1) * 128 + kc * 32);
            cpa16(s0 + lrow0 * ROWS + lseg0 * 16,         gWhi + gb0 + lseg0 * 8);
            cpa16(s0 + lrow1 * ROWS + lseg1 * 16,         gWhi + gb1 + lseg1 * 8);
            cpa16(s0 + 10240 + lrow0 * ROWS + lseg0 * 16, gWlo + gb0 + lseg0 * 8);
            cpa16(s0 + 10240 + lrow1 * ROWS + lseg1 * 16, gWlo + gb1 + lseg1 * 8);
        }
        {
            size_t gb0 = ((size_t)(bp * 128 + lrow0) * 128 + kc * 32);
            size_t gb1 = ((size_t)(bp * 128 + lrow1) * 128 + kc * 32);
            cpa16(s0 + 20480 + lrow0 * ROWS + lseg0 * 16, gXhi + gb0 + lseg0 * 8);
            cpa16(s0 + 20480 + lrow1 * ROWS + lseg1 * 16, gXhi + gb1 + lseg1 * 8);
            cpa16(s0 + 30720 + lrow0 * ROWS + lseg0 * 16, gXlo + gb0 + lseg0 * 8);
            cpa16(s0 + 30720 + lrow1 * ROWS + lseg1 * 16, gXlo + gb1 + lseg1 * 8);
        }
    };

    issue(0, 0);
    asm volatile("cp.async.commit_group;");

    for (int kc = 0; kc < 4; kc++) {
        const int st = kc & 1;
        if (kc < 3) issue(kc + 1, st ^ 1);
        asm volatile("cp.async.commit_group;");
        if (kc < 3) asm volatile("cp.async.wait_group 1;");
        else        asm volatile("cp.async.wait_group 0;");
        __syncthreads();

        const uint32_t sAhi_b = sbase + st * ASTAGE;
        const uint32_t sAlo_b = sAhi_b + 10240;
        const uint32_t sBhi_b = sAhi_b + 20480;
        const uint32_t sBlo_b = sAhi_b + 30720;

#pragma unroll
        for (int ks = 0; ks < 2; ks++) {
            const int klb = ks * 32;
            uint32_t ahi[4][4], alo_[4][4];
#pragma unroll
            for (int i = 0; i < 4; i++) {
                uint32_t ao = aOff + klb + (uint32_t)i * 16 * ROWS;
                ldsm_x4(ahi[i][0], ahi[i][1], ahi[i][2], ahi[i][3], sAhi_b + ao);
                ldsm_x4(alo_[i][0], alo_[i][1], alo_[i][2], alo_[i][3], sAlo_b + ao);
            }
#pragma unroll
            for (int j = 0; j < 4; j++) {
                uint32_t bo_ = bOff + klb + (uint32_t)j * 8 * ROWS;
                uint32_t bh0, bh1, bl0, bl1;
                ldsm_x2(bh0, bh1, sBhi_b + bo_);
                ldsm_x2(bl0, bl1, sBlo_b + bo_);
                // term-outer, i-inner: 4 independent accumulators between reuses
#pragma unroll
                for (int i = 0; i < 4; i++)
                    mma16816(acc[i][j], ahi[i][0], ahi[i][1], ahi[i][2], ahi[i][3], bh0, bh1);
#pragma unroll
                for (int i = 0; i < 4; i++)
                    mma16816(acc[i][j], ahi[i][0], ahi[i][1], ahi[i][2], ahi[i][3], bl0, bl1);
#pragma unroll
                for (int i = 0; i < 4; i++)
                    mma16816(acc[i][j], alo_[i][0], alo_[i][1], alo_[i][2], alo_[i][3], bh0, bh1);
            }
        }
        __syncthreads();
    }

    const int g = lane >> 2;
    const int q = lane & 3;

    if (bo < 4) {
        // ---- fused q.k epilogue: warp_m's 64 rows = [32 q | 32 k] of one head.
        const int head = bo * 2 + warp_m;
        float* tb = g_t + (size_t)head * NP;
#pragma unroll
        for (int j = 0; j < 4; j++) {
            float s0 = 0.f, s1 = 0.f;
#pragma unroll
            for (int i = 0; i < 2; i++) {
                s0 += acc[i][j][0] * acc[i + 2][j][0] + acc[i][j][2] * acc[i + 2][j][2];
                s1 += acc[i][j][1] * acc[i + 2][j][1] + acc[i][j][3] * acc[i + 2][j][3];
            }
#pragma unroll
            for (int m = 4; m <= 16; m <<= 1) {
                s0 += __shfl_xor_sync(0xffffffffu, s0, m);
                s1 += __shfl_xor_sync(0xffffffffu, s1, m);
            }
            if (g == 0) {
                int p = bp * 128 + warp_n * 32 + j * 8 + 2 * q;
                *(float2*)(tb + p) = make_float2(s0 * 0.0625f, s1 * 0.0625f);
            }
        }
    } else {
        // ---- v epilogue ----
#pragma unroll
        for (int i = 0; i < 4; i++) {
            int o = (bo - 4) * 128 + warp_m * 64 + i * 16 + g;
#pragma unroll
            for (int j = 0; j < 4; j++) {
                int p = bp * 128 + warp_n * 32 + j * 8 + 2 * q;
                *(float2*)(g_v + (size_t)o * NP + p)       = make_float2(acc[i][j][0], acc[i][j][1]);
                *(float2*)(g_v + (size_t)(o + 8) * NP + p) = make_float2(acc[i][j][2], acc[i][j][3]);
            }
        }
    }
}

// ---------------------------------------------------------------------------
// Kernel 3: 3x3 regional softmax + weighted V sum.
// grid (192, 16): block = row h, head (y>>1), 16-channel half (y&1).
// Phase 1: 192 threads -> softmax weights for this head's 192 w positions.
// Phase 2: thread = (w-quad, ch-sub); weights reg-resident, loaded ONCE.
// OOB slots contribute score 0 (exp(0-m)); OOB v contributes 0.
// ---------------------------------------------------------------------------
__global__ __launch_bounds__(192) void attn(float* __restrict__ out)
{
    __shared__ float w9s[9][192];

    const int h    = blockIdx.x;        // 0..191
    const int head = blockIdx.y >> 1;   // 0..7
    const int chf  = blockIdx.y & 1;    // 0..1 channel half
    const int tid  = threadIdx.x;       // 0..191

    // ---- phase 1: softmax weights for (h, head) ----
    {
        const int w = tid;
        const float* tb = g_t + (size_t)head * NP;
        float sc[9];
#pragma unroll
        for (int s = 0; s < 9; s++) {
            int hh = h + s / 3 - 1;
            int ww = w + s % 3 - 1;
            float v = 0.f;
            if ((unsigned)hh < 192u && (unsigned)ww < 192u)
                v = tb[hh * WW + ww];
            sc[s] = v;
        }
        float m = sc[0];
#pragma unroll
        for (int s = 1; s < 9; s++) m = fmaxf(m, sc[s]);
        float sum = 0.f;
#pragma unroll
        for (int s = 0; s < 9; s++) { float e = __expf(sc[s] - m); sc[s] = e; sum += e; }
        float inv = 1.0f / sum;
#pragma unroll
        for (int s = 0; s < 9; s++) w9s[s][w] = sc[s] * inv;
    }
    __syncthreads();

    // ---- phase 2: 16 channels, 4 per iteration ----
    const int w0  = (tid % 48) * 4;
    const int cl4 = tid / 48;

    float4 Wt[3][3];
#pragma unroll
    for (int s = 0; s < 9; s++)
        Wt[s / 3][s % 3] = *(const float4*)&w9s[s][w0];

    const int ch0 = head * 32 + chf * 16 + cl4;

#pragma unroll 2
    for (int co = 0; co < 4; co++) {
        const int ch = ch0 + co * 4;
        const float* vb = g_v + (size_t)ch * NP;

        float o0 = 0.f, o1 = 0.f, o2 = 0.f, o3 = 0.f;
#pragma unroll
        for (int dh = 0; dh < 3; dh++) {
            int hh = h + dh - 1;
            if ((unsigned)hh >= 192u) continue;
            const float* row = vb + hh * WW;
            float4 c = *(const float4*)(row + w0);
            float left  = (w0 > 0)   ? row[w0 - 1] : 0.f;
            float right = (w0 < 188) ? row[w0 + 4] : 0.f;
            o0 += Wt[dh][0].x * left + Wt[dh][1].x * c.x + Wt[dh][2].x * c.y;
            o1 += Wt[dh][0].y * c.x  + Wt[dh][1].y * c.y + Wt[dh][2].y * c.z;
            o2 += Wt[dh][0].z * c.y  + Wt[dh][1].z * c.z + Wt[dh][2].z * c.w;
            o3 += Wt[dh][0].w * c.z  + Wt[dh][1].w * c.w + Wt[dh][2].w * right;
        }
        *(float4*)(out + (size_t)ch * NP + h * WW + w0) = make_float4(o0, o1, o2, o3);
    }
}

// ---------------------------------------------------------------------------
extern "C" void kernel_launch(void* const* d_in, const int* in_sizes, int n_in,
                              void* d_out, int out_size)
{
    const float* x  = (const float*)d_in[0];
    const float* wq = (const float*)d_in[1];
    const float* wk = (const float*)d_in[2];
    const float* wv = (const float*)d_in[3];
    float* out = (float*)d_out;

    cudaFuncSetAttribute(gemm_qkv, cudaFuncAttributeMaxDynamicSharedMemorySize, 2 * ASTAGE);

    conv_w<<<96, 256>>>(wq, wk, wv);
    conv_x<<<NP / 32, 256>>>(x);

    dim3 g1(NP / 128, OC / 128);     // (288, 6)
    gemm_qkv<<<g1, 256, 2 * ASTAGE>>>();

    dim3 g3(HH, 16);                 // (192, 16)
    attn<<<g3, 192>>>(out);
}

// round 9
// speedup vs baseline: 3.0108x; 1.0138x over previous
#include <cuda_runtime.h>
#include <cuda_bf16.h>
#include <cstdint>

// Problem constants
#define C_IN   128
#define OC     768            // 512 qk-interleaved + 256 v
#define NP     36864          // 192*192 pixels
#define HH     192
#define WW     192
#define NHEAD  8

// Scratch
__device__ float g_v[(size_t)256 * NP];      // v [ch][pixel]
__device__ float g_t[(size_t)NHEAD * NP];    // scores
__device__ __align__(16) unsigned short gWhi[(size_t)OC * C_IN];   // bf16 bits, [o][c], head-interleaved qk
__device__ __align__(16) unsigned short gWlo[(size_t)OC * C_IN];
__device__ __align__(16) unsigned short gXhi[(size_t)NP * C_IN];   // bf16 bits, [p][c]
__device__ __align__(16) unsigned short gXlo[(size_t)NP * C_IN];

// ---------------------------------------------------------------------------
__device__ __forceinline__ void bf16_split(float f, unsigned short& h, unsigned short& l)
{
    __nv_bfloat16 hb = __float2bfloat16(f);
    float r = f - __bfloat162float(hb);
    __nv_bfloat16 lb = __float2bfloat16(r);
    h = __bfloat16_as_ushort(hb);
    l = __bfloat16_as_ushort(lb);
}

__device__ __forceinline__ void mma16816(float c[4],
                                         uint32_t a0, uint32_t a1, uint32_t a2, uint32_t a3,
                                         uint32_t b0, uint32_t b1)
{
    asm volatile(
        "mma.sync.aligned.m16n8k16.row.col.f32.bf16.bf16.f32 "
        "{%0,%1,%2,%3}, {%4,%5,%6,%7}, {%8,%9}, {%0,%1,%2,%3};\n"
        : "+f"(c[0]), "+f"(c[1]), "+f"(c[2]), "+f"(c[3])
        : "r"(a0), "r"(a1), "r"(a2), "r"(a3), "r"(b0), "r"(b1));
}

__device__ __forceinline__ void ldsm_x4(uint32_t& r0, uint32_t& r1, uint32_t& r2, uint32_t& r3,
                                        uint32_t saddr)
{
    asm volatile("ldmatrix.sync.aligned.m8n8.x4.shared.b16 {%0,%1,%2,%3}, [%4];"
                 : "=r"(r0), "=r"(r1), "=r"(r2), "=r"(r3) : "r"(saddr));
}

__device__ __forceinline__ void ldsm_x2(uint32_t& r0, uint32_t& r1, uint32_t saddr)
{
    asm volatile("ldmatrix.sync.aligned.m8n8.x2.shared.b16 {%0,%1}, [%2];"
                 : "=r"(r0), "=r"(r1) : "r"(saddr));
}

__device__ __forceinline__ void cpa16(uint32_t saddr, const void* g)
{
    asm volatile("cp.async.cg.shared.global [%0], [%1], 16;" :: "r"(saddr), "l"(g));
}

// ---------------------------------------------------------------------------
// Pre-pass A: convert W to bf16 hi/lo with head-interleaved q/k layout:
// rows [0,512): block of 64 per head = [wq head rows 0..31 | wk head rows 0..31]
// rows [512,768): wv. grid 96 x 256.
// ---------------------------------------------------------------------------
__global__ __launch_bounds__(256) void conv_w(
    const float* __restrict__ wq, const float* __restrict__ wk, const float* __restrict__ wv)
{
    int idx = (blockIdx.x * 256 + threadIdx.x) * 4;
    int row = idx >> 7, col = idx & 127;
    const float* src;
    if (row < 512) {
        int head = row >> 6, sub = row & 63;
        src = (sub < 32) ? (wq + (size_t)(head * 32 + sub) * 128)
                         : (wk + (size_t)(head * 32 + sub - 32) * 128);
    } else {
        src = wv + (size_t)(row - 512) * 128;
    }
    float4 v = *(const float4*)(src + col);
    unsigned short h[4], l[4];
    bf16_split(v.x, h[0], l[0]); bf16_split(v.y, h[1], l[1]);
    bf16_split(v.z, h[2], l[2]); bf16_split(v.w, h[3], l[3]);
    *(uint2*)(gWhi + idx) = make_uint2((uint32_t)h[0] | ((uint32_t)h[1] << 16),
                                       (uint32_t)h[2] | ((uint32_t)h[3] << 16));
    *(uint2*)(gWlo + idx) = make_uint2((uint32_t)l[0] | ((uint32_t)l[1] << 16),
                                       (uint32_t)l[2] | ((uint32_t)l[3] << 16));
}

// ---------------------------------------------------------------------------
// Pre-pass B: transpose+convert x [c][p] -> gX[p][c] bf16 hi/lo.
// ---------------------------------------------------------------------------
__global__ __launch_bounds__(256) void conv_x(const float* __restrict__ x)
{
    __shared__ float s[128][33];
    const int p0  = blockIdx.x * 32;
    const int tid = threadIdx.x;
    const int pr  = tid & 31, cr = tid >> 5;
#pragma unroll
    for (int l = 0; l < 16; l++) {
        int c = cr + l * 8;
        s[c][pr] = x[(size_t)c * NP + p0 + pr];
    }
    __syncthreads();
    const int p = tid >> 3, kq = tid & 7;
    __align__(16) unsigned short hv[16], lv[16];
#pragma unroll
    for (int i = 0; i < 16; i++)
        bf16_split(s[kq * 16 + i][p], hv[i], lv[i]);
    size_t base = (size_t)(p0 + p) * 128 + kq * 16;
    *(uint4*)(gXhi + base)     = ((const uint4*)hv)[0];
    *(uint4*)(gXhi + base + 8) = ((const uint4*)hv)[1];
    *(uint4*)(gXlo + base)     = ((const uint4*)lv)[0];
    *(uint4*)(gXlo + base + 8) = ((const uint4*)lv)[1];
}

// ---------------------------------------------------------------------------
// Kernel 1: QKV projection GEMM + fused q.k epilogue.
// CTA 128(o) x 128(p). bo<4: q/k heads (2 per CTA) -> write t only.
// bo in {4,5}: v -> write g_v. Double-buffered cp.async, smem 80 KB.
// ---------------------------------------------------------------------------
#define ROWS   80
#define ASTAGE 40960

__global__ __launch_bounds__(256, 2) void gemm_qkv()
{
    extern __shared__ unsigned char dsm[];
    const uint32_t sbase = (uint32_t)__cvta_generic_to_shared(dsm);

    const int bp   = blockIdx.x;
    const int bo   = blockIdx.y;
    const int tid  = threadIdx.x;
    const int wid  = tid >> 5;
    const int lane = tid & 31;
    const int warp_m = wid >> 2;
    const int warp_n = wid & 3;

    const int lrow0 = tid >> 2, lseg0 = tid & 3;
    const int lrow1 = (tid + 256) >> 2, lseg1 = tid & 3;

    const int a_mat  = lane >> 3;
    const int a_rowl = ((a_mat & 1) << 3) + (lane & 7);
    const int a_seg  = a_mat >> 1;
    const uint32_t aOff = (uint32_t)(warp_m * 64 + a_rowl) * ROWS + a_seg * 16;
    const int b_rowl = lane & 7;
    const int b_seg  = (lane >> 3) & 1;
    const uint32_t bOff = (uint32_t)(warp_n * 32 + b_rowl) * ROWS + b_seg * 16;

    float acc[4][4][4];
#pragma unroll
    for (int i = 0; i < 4; i++)
#pragma unroll
        for (int j = 0; j < 4; j++)
#pragma unroll
            for (int r = 0; r < 4; r++) acc[i][j][r] = 0.f;

    auto issue = [&](int kc, int st) {
        const uint32_t s0 = sbase + st * ASTAGE;
        {
            size_t gb0 = ((size_t)(bo * 128 + lrow0) * 128 + kc * 32);
            size_t gb1 = ((size_t)(bo * 128 + lrow1) * 128 + kc * 32);
            cpa16(s0 + lrow0 * ROWS + lseg0 * 16,         gWhi + gb0 + lseg0 * 8);
            cpa16(s0 + lrow1 * ROWS + lseg1 * 16,         gWhi + gb1 + lseg1 * 8);
            cpa16(s0 + 10240 + lrow0 * ROWS + lseg0 * 16, gWlo + gb0 + lseg0 * 8);
            cpa16(s0 + 10240 + lrow1 * ROWS + lseg1 * 16, gWlo + gb1 + lseg1 * 8);
        }
        {
            size_t gb0 = ((size_t)(bp * 128 + lrow0) * 128 + kc * 32);
            size_t gb1 = ((size_t)(bp * 128 + lrow1) * 128 + kc * 32);
            cpa16(s0 + 20480 + lrow0 * ROWS + lseg0 * 16, gXhi + gb0 + lseg0 * 8);
            cpa16(s0 + 20480 + lrow1 * ROWS + lseg1 * 16, gXhi + gb1 + lseg1 * 8);
            cpa16(s0 + 30720 + lrow0 * ROWS + lseg0 * 16, gXlo + gb0 + lseg0 * 8);
            cpa16(s0 + 30720 + lrow1 * ROWS + lseg1 * 16, gXlo + gb1 + lseg1 * 8);
        }
    };

    issue(0, 0);
    asm volatile("cp.async.commit_group;");

    for (int kc = 0; kc < 4; kc++) {
        const int st = kc & 1;
        if (kc < 3) issue(kc + 1, st ^ 1);
        asm volatile("cp.async.commit_group;");
        if (kc < 3) asm volatile("cp.async.wait_group 1;");
        else        asm volatile("cp.async.wait_group 0;");
        __syncthreads();

        const uint32_t sAhi_b = sbase + st * ASTAGE;
        const uint32_t sAlo_b = sAhi_b + 10240;
        const uint32_t sBhi_b = sAhi_b + 20480;
        const uint32_t sBlo_b = sAhi_b + 30720;

#pragma unroll
        for (int ks = 0; ks < 2; ks++) {
            const int klb = ks * 32;
            uint32_t ahi[4][4], alo_[4][4];
#pragma unroll
            for (int i = 0; i < 4; i++) {
                uint32_t ao = aOff + klb + (uint32_t)i * 16 * ROWS;
                ldsm_x4(ahi[i][0], ahi[i][1], ahi[i][2], ahi[i][3], sAhi_b + ao);
                ldsm_x4(alo_[i][0], alo_[i][1], alo_[i][2], alo_[i][3], sAlo_b + ao);
            }
#pragma unroll
            for (int j = 0; j < 4; j++) {
                uint32_t bo_ = bOff + klb + (uint32_t)j * 8 * ROWS;
                uint32_t bh0, bh1, bl0, bl1;
                ldsm_x2(bh0, bh1, sBhi_b + bo_);
                ldsm_x2(bl0, bl1, sBlo_b + bo_);
                // term-outer, i-inner: 4 independent accumulators between reuses
#pragma unroll
                for (int i = 0; i < 4; i++)
                    mma16816(acc[i][j], ahi[i][0], ahi[i][1], ahi[i][2], ahi[i][3], bh0, bh1);
#pragma unroll
                for (int i = 0; i < 4; i++)
                    mma16816(acc[i][j], ahi[i][0], ahi[i][1], ahi[i][2], ahi[i][3], bl0, bl1);
#pragma unroll
                for (int i = 0; i < 4; i++)
                    mma16816(acc[i][j], alo_[i][0], alo_[i][1], alo_[i][2], alo_[i][3], bh0, bh1);
            }
        }
        __syncthreads();
    }

    const int g = lane >> 2;
    const int q = lane & 3;

    if (bo < 4) {
        // ---- fused q.k epilogue: warp_m's 64 rows = [32 q | 32 k] of one head.
        const int head = bo * 2 + warp_m;
        float* tb = g_t + (size_t)head * NP;
#pragma unroll
        for (int j = 0; j < 4; j++) {
            float s0 = 0.f, s1 = 0.f;
#pragma unroll
            for (int i = 0; i < 2; i++) {
                s0 += acc[i][j][0] * acc[i + 2][j][0] + acc[i][j][2] * acc[i + 2][j][2];
                s1 += acc[i][j][1] * acc[i + 2][j][1] + acc[i][j][3] * acc[i + 2][j][3];
            }
#pragma unroll
            for (int m = 4; m <= 16; m <<= 1) {
                s0 += __shfl_xor_sync(0xffffffffu, s0, m);
                s1 += __shfl_xor_sync(0xffffffffu, s1, m);
            }
            if (g == 0) {
                int p = bp * 128 + warp_n * 32 + j * 8 + 2 * q;
                *(float2*)(tb + p) = make_float2(s0 * 0.0625f, s1 * 0.0625f);
            }
        }
    } else {
        // ---- v epilogue ----
#pragma unroll
        for (int i = 0; i < 4; i++) {
            int o = (bo - 4) * 128 + warp_m * 64 + i * 16 + g;
#pragma unroll
            for (int j = 0; j < 4; j++) {
                int p = bp * 128 + warp_n * 32 + j * 8 + 2 * q;
                *(float2*)(g_v + (size_t)o * NP + p)       = make_float2(acc[i][j][0], acc[i][j][1]);
                *(float2*)(g_v + (size_t)(o + 8) * NP + p) = make_float2(acc[i][j][2], acc[i][j][3]);
            }
        }
    }
}

// ---------------------------------------------------------------------------
// Kernel 3: 3x3 regional softmax + weighted V sum.
// grid (192, 16): block = row h, head (y>>1), 16-channel half (y&1).
// Phase 1: softmax weights for this head's 192 w positions (smem).
// Phase 2: dh-OUTER, channel-INNER: only 12 weight regs live at a time,
// 16-reg accumulator block o[4][4]; launch_bounds(192,7) -> <=48 regs,
// 7 blocks/SM (~66% occ vs 42% before).
// OOB slots contribute score 0 (exp(0-m)); OOB v contributes 0.
// ---------------------------------------------------------------------------
__global__ __launch_bounds__(192, 7) void attn(float* __restrict__ out)
{
    __shared__ float w9s[9][192];

    const int h    = blockIdx.x;        // 0..191
    const int head = blockIdx.y >> 1;   // 0..7
    const int chf  = blockIdx.y & 1;    // 0..1 channel half
    const int tid  = threadIdx.x;       // 0..191

    // ---- phase 1: softmax weights for (h, head) ----
    {
        const int w = tid;
        const float* tb = g_t + (size_t)head * NP;
        float sc[9];
#pragma unroll
        for (int s = 0; s < 9; s++) {
            int hh = h + s / 3 - 1;
            int ww = w + s % 3 - 1;
            float v = 0.f;
            if ((unsigned)hh < 192u && (unsigned)ww < 192u)
                v = tb[hh * WW + ww];
            sc[s] = v;
        }
        float m = sc[0];
#pragma unroll
        for (int s = 1; s < 9; s++) m = fmaxf(m, sc[s]);
        float sum = 0.f;
#pragma unroll
        for (int s = 0; s < 9; s++) { float e = __expf(sc[s] - m); sc[s] = e; sum += e; }
        float inv = 1.0f / sum;
#pragma unroll
        for (int s = 0; s < 9; s++) w9s[s][w] = sc[s] * inv;
    }
    __syncthreads();

    // ---- phase 2: dh-outer, 4-channel inner ----
    const int w0  = (tid % 48) * 4;
    const int cl4 = tid / 48;                       // 0..3
    const int ch0 = head * 32 + chf * 16 + cl4;     // channels ch0 + {0,4,8,12}

    float o[4][4];
#pragma unroll
    for (int c = 0; c < 4; c++)
#pragma unroll
        for (int r = 0; r < 4; r++) o[c][r] = 0.f;

    const float* vbase = g_v + (size_t)ch0 * NP + w0;

#pragma unroll
    for (int dh = 0; dh < 3; dh++) {
        int hh = h + dh - 1;
        if ((unsigned)hh >= 192u) continue;

        float4 Wa = *(const float4*)&w9s[dh * 3 + 0][w0];
        float4 Wb = *(const float4*)&w9s[dh * 3 + 1][w0];
        float4 Wc = *(const float4*)&w9s[dh * 3 + 2][w0];

        const float* rb = vbase + hh * WW;
#pragma unroll
        for (int co = 0; co < 4; co++) {
            const float* row = rb + (size_t)(co * 4) * NP;
            float4 c = *(const float4*)row;
            float left  = (w0 > 0)   ? row[-1] : 0.f;
            float right = (w0 < 188) ? row[4]  : 0.f;
            o[co][0] += Wa.x * left + Wb.x * c.x + Wc.x * c.y;
            o[co][1] += Wa.y * c.x  + Wb.y * c.y + Wc.y * c.z;
            o[co][2] += Wa.z * c.y  + Wb.z * c.z + Wc.z * c.w;
            o[co][3] += Wa.w * c.z  + Wb.w * c.w + Wc.w * right;
        }
    }

    float* ob = out + (size_t)ch0 * NP + h * WW + w0;
#pragma unroll
    for (int co = 0; co < 4; co++)
        *(float4*)(ob + (size_t)(co * 4) * NP) = make_float4(o[co][0], o[co][1], o[co][2], o[co][3]);
}

// ---------------------------------------------------------------------------
extern "C" void kernel_launch(void* const* d_in, const int* in_sizes, int n_in,
                              void* d_out, int out_size)
{
    const float* x  = (const float*)d_in[0];
    const float* wq = (const float*)d_in[1];
    const float* wk = (const float*)d_in[2];
    const float* wv = (const float*)d_in[3];
    float* out = (float*)d_out;

    cudaFuncSetAttribute(gemm_qkv, cudaFuncAttributeMaxDynamicSharedMemorySize, 2 * ASTAGE);

    conv_w<<<96, 256>>>(wq, wk, wv);
    conv_x<<<NP / 32, 256>>>(x);

    dim3 g1(NP / 128, OC / 128);     // (288, 6)
    gemm_qkv<<<g1, 256, 2 * ASTAGE>>>();

    dim3 g3(HH, 16);                 // (192, 16)
    attn<<<g3, 192>>>(out);
}